// round 4
// baseline (speedup 1.0000x reference)
#include <cuda_runtime.h>
#include <math.h>

// ---------------- problem constants ----------------
#define Bn 4
#define Nn 1024
#define Mn 512
#define Dn 512
#define Pn 256
#define Hn 8
#define DHn 64
#define Ln 6
#define FIn 2048
#define NK1 1025   // N + 1 (null kv)
#define NK2 513    // M + 1

#define CDIV(a,b) (((a)+(b)-1)/(b))

// ---------------- scratch (device globals; no allocation) ----------------
__device__ float g_x   [Bn*Nn*Dn];        // running residual stream
__device__ float g_xn  [Bn*Nn*Dn];        // layernormed x
__device__ float g_ctxn[Bn*Mn*Pn];        // layernormed context
__device__ float g_q   [Bn*Nn*Hn*DHn];    // q projection (b,n,h,d)
__device__ float g_q2  [Bn*Nn*Hn*DHn];    // rotated q
__device__ float g_kvt [Bn*Nn*2*DHn];     // kv projection (rows, 128)
__device__ float g_k   [Bn*NK1*DHn];      // assembled K incl null row
__device__ float g_v   [Bn*NK1*DHn];
__device__ float g_sim [(size_t)Bn*Hn*Nn*NK1]; // attention logits/probs
__device__ float g_att [Bn*Nn*Hn*DHn];    // attention output (b,n,h,d)
__device__ float g_proj[Bn*Nn*Dn];        // post-wo / ff2 staging
__device__ float g_ff1 [(size_t)Bn*Nn*2*FIn];
__device__ float g_ffh [(size_t)Bn*Nn*FIn];
__device__ float g_bias[(size_t)Hn*Nn*NK1]; // rel-pos bias + causal mask

// ---------------- reductions ----------------
__device__ __forceinline__ float warpSum(float v) {
    #pragma unroll
    for (int o = 16; o > 0; o >>= 1) v += __shfl_xor_sync(0xffffffffu, v, o);
    return v;
}
__device__ __forceinline__ float warpMax(float v) {
    #pragma unroll
    for (int o = 16; o > 0; o >>= 1) v = fmaxf(v, __shfl_xor_sync(0xffffffffu, v, o));
    return v;
}
__device__ float blockSum(float v) {
    __shared__ float sh[32];
    int lane = threadIdx.x & 31, w = threadIdx.x >> 5;
    int nw = blockDim.x >> 5;
    v = warpSum(v);
    __syncthreads();
    if (lane == 0) sh[w] = v;
    __syncthreads();
    float r = (lane < nw) ? sh[lane] : 0.f;
    return warpSum(r);
}
__device__ float blockMax(float v) {
    __shared__ float sh[32];
    int lane = threadIdx.x & 31, w = threadIdx.x >> 5;
    int nw = blockDim.x >> 5;
    v = warpMax(v);
    __syncthreads();
    if (lane == 0) sh[w] = v;
    __syncthreads();
    float r = (lane < nw) ? sh[lane] : -3.4e38f;
    return warpMax(r);
}

// ---------------- generic batched fp32 GEMM ----------------
// C[M,N] = A[M,K] @ B[K,N]  (transB: B stored as [N,K] row-major)
// batch bz -> (outer ob, inner ib): ptr += ob*outerStride + ib*innerStride
#define GBM 64
#define GBN 64
#define GBK 16
__global__ void gemm_k(
    const float* __restrict__ A, int lda, long aO, long aI,
    const float* __restrict__ Bm, int ldb, long bO, long bI,
    float* __restrict__ C, int ldc, long cO, long cI,
    int M, int N, int K, int inner, int transB, int accum)
{
    __shared__ float As[GBK][GBM + 4];
    __shared__ float Bs[GBK][GBN + 4];
    int bz = blockIdx.z;
    int ob = bz / inner, ib = bz - ob * inner;
    A  += (size_t)ob * aO + (size_t)ib * aI;
    Bm += (size_t)ob * bO + (size_t)ib * bI;
    C  += (size_t)ob * cO + (size_t)ib * cI;
    int row0 = blockIdx.y * GBM;
    int col0 = blockIdx.x * GBN;
    int tid = threadIdx.x;
    int tx = tid & 15, ty = tid >> 4;
    float acc[4][4] = {};
    for (int k0 = 0; k0 < K; k0 += GBK) {
        #pragma unroll
        for (int i = 0; i < 4; i++) {
            int idx = tid + i * 256;
            int m = idx >> 4, kk = idx & 15;
            int gr = row0 + m, gk = k0 + kk;
            As[kk][m] = (gr < M && gk < K) ? A[(size_t)gr * lda + gk] : 0.f;
        }
        if (!transB) {
            #pragma unroll
            for (int i = 0; i < 4; i++) {
                int idx = tid + i * 256;
                int kk = idx >> 6, n = idx & 63;
                int gk = k0 + kk, gn = col0 + n;
                Bs[kk][n] = (gk < K && gn < N) ? Bm[(size_t)gk * ldb + gn] : 0.f;
            }
        } else {
            #pragma unroll
            for (int i = 0; i < 4; i++) {
                int idx = tid + i * 256;
                int n = idx >> 4, kk = idx & 15;
                int gk = k0 + kk, gn = col0 + n;
                Bs[kk][n] = (gk < K && gn < N) ? Bm[(size_t)gn * ldb + gk] : 0.f;
            }
        }
        __syncthreads();
        #pragma unroll
        for (int kk = 0; kk < GBK; kk++) {
            float a[4], b[4];
            #pragma unroll
            for (int i = 0; i < 4; i++) a[i] = As[kk][ty * 4 + i];
            #pragma unroll
            for (int j = 0; j < 4; j++) b[j] = Bs[kk][tx * 4 + j];
            #pragma unroll
            for (int i = 0; i < 4; i++)
                #pragma unroll
                for (int j = 0; j < 4; j++)
                    acc[i][j] += a[i] * b[j];
        }
        __syncthreads();
    }
    #pragma unroll
    for (int i = 0; i < 4; i++) {
        int gr = row0 + ty * 4 + i;
        if (gr >= M) continue;
        #pragma unroll
        for (int j = 0; j < 4; j++) {
            int gn = col0 + tx * 4 + j;
            if (gn >= N) continue;
            size_t off = (size_t)gr * ldc + gn;
            if (accum) C[off] += acc[i][j]; else C[off] = acc[i][j];
        }
    }
}

// ---------------- layernorm (one block per row) ----------------
__global__ void ln_k(const float* __restrict__ x, const float* __restrict__ g,
                     float* __restrict__ out, int C)
{
    size_t row = blockIdx.x;
    const float* xr = x + row * C;
    float s = 0.f;
    for (int c = threadIdx.x; c < C; c += blockDim.x) s += xr[c];
    float mu = blockSum(s) / C;
    float v = 0.f;
    for (int c = threadIdx.x; c < C; c += blockDim.x) { float d = xr[c] - mu; v += d * d; }
    float rstd = rsqrtf(blockSum(v) / C + 1e-5f);
    float* orow = out + row * C;
    for (int c = threadIdx.x; c < C; c += blockDim.x) orow[c] = (xr[c] - mu) * rstd * g[c];
}

// x[row] += LN(p[row]) * g   (residual + output-norm fused)
__global__ void lnadd_k(const float* __restrict__ p, const float* __restrict__ g,
                        float* __restrict__ x, int C)
{
    size_t row = blockIdx.x;
    const float* pr = p + row * C;
    float s = 0.f;
    for (int c = threadIdx.x; c < C; c += blockDim.x) s += pr[c];
    float mu = blockSum(s) / C;
    float v = 0.f;
    for (int c = threadIdx.x; c < C; c += blockDim.x) { float d = pr[c] - mu; v += d * d; }
    float rstd = rsqrtf(blockSum(v) / C + 1e-5f);
    float* xr = x + row * C;
    for (int c = threadIdx.x; c < C; c += blockDim.x) xr[c] += (pr[c] - mu) * rstd * g[c];
}

// final "stable" layernorm: x /= max(x) then LN
__global__ void lnfinal_k(const float* __restrict__ x, const float* __restrict__ g,
                          float* __restrict__ out)
{
    const int C = Dn;
    size_t row = blockIdx.x;
    const float* xr = x + row * C;
    float m = -3.4e38f;
    for (int c = threadIdx.x; c < C; c += blockDim.x) m = fmaxf(m, xr[c]);
    m = blockMax(m);
    float inv = 1.f / m;
    float s = 0.f;
    for (int c = threadIdx.x; c < C; c += blockDim.x) s += xr[c] * inv;
    float mu = blockSum(s) / C;
    float v = 0.f;
    for (int c = threadIdx.x; c < C; c += blockDim.x) { float d = xr[c] * inv - mu; v += d * d; }
    float rstd = rsqrtf(blockSum(v) / C + 1e-5f);
    float* orow = out + row * C;
    for (int c = threadIdx.x; c < C; c += blockDim.x) orow[c] = (xr[c] * inv - mu) * rstd * g[c];
}

// ---------------- softmax over one logits row, with scale + optional bias ----------------
__global__ void softmax_k(float* __restrict__ sim, const float* __restrict__ bias,
                          int Nk, float scale)
{
    size_t row = blockIdx.x;     // (b*H + h)*N + i
    float* sr = sim + row * (size_t)Nk;
    const float* br = nullptr;
    if (bias) {
        int i = (int)(row % Nn);
        int h = (int)((row / Nn) % Hn);
        br = bias + ((size_t)h * Nn + i) * (size_t)Nk;
    }
    float mx = -3.4e38f;
    for (int j = threadIdx.x; j < Nk; j += blockDim.x) {
        float v = sr[j] * scale + (br ? br[j] : 0.f);
        sr[j] = v;
        mx = fmaxf(mx, v);
    }
    mx = blockMax(mx);
    float s = 0.f;
    for (int j = threadIdx.x; j < Nk; j += blockDim.x) {
        float e = expf(sr[j] - mx);
        sr[j] = e;
        s += e;
    }
    s = blockSum(s);
    float inv = 1.f / s;
    for (int j = threadIdx.x; j < Nk; j += blockDim.x) sr[j] *= inv;
}

// ---------------- rotary on q: (b,n,h,64), dims 0..31 rotated ----------------
__global__ void rotq_k(const float* __restrict__ q, float* __restrict__ o)
{
    size_t idx = (size_t)blockIdx.x * blockDim.x + threadIdx.x;
    if (idx >= (size_t)Bn * Nn * Hn * DHn) return;
    int c = (int)(idx & 63);
    float val = q[idx];
    if (c < 32) {
        int n = (int)((idx >> 9) & (Nn - 1));    // token index
        int p = c & 15;
        float invf = powf(10000.f, -(float)p / 16.f);
        float f = (float)n * invf;
        float partner = (c < 16) ? q[idx + 16] : q[idx - 16];
        val = val * cosf(f) + ((c < 16) ? -partner : partner) * sinf(f);
    }
    o[idx] = val;
}

// ---------------- assemble K/V with null row, optional rotary on K ----------------
__global__ void asmkv_k(const float* __restrict__ kvt, const float* __restrict__ nkv,
                        float* __restrict__ kb, float* __restrict__ vb,
                        int Nsrc, int useRot)
{
    int NkL = Nsrc + 1;
    size_t total = (size_t)Bn * NkL * DHn;
    size_t idx = (size_t)blockIdx.x * blockDim.x + threadIdx.x;
    if (idx >= total) return;
    int c = (int)(idx & 63);
    size_t bj = idx >> 6;
    int j = (int)(bj % NkL);
    float kv, vv;
    if (j == 0) {
        kv = nkv[c];
        vv = nkv[DHn + c];
    } else {
        const float* rp = kvt + ((bj / NkL) * Nsrc + (j - 1)) * (size_t)(2 * DHn);
        kv = rp[c];
        vv = rp[DHn + c];
        if (useRot && c < 32) {
            int p = c & 15;
            float invf = powf(10000.f, -(float)p / 16.f);
            float f = (float)(j - 1) * invf;
            float partner = (c < 16) ? rp[c + 16] : rp[c - 16];
            kv = kv * cosf(f) + ((c < 16) ? -partner : partner) * sinf(f);
        }
    }
    kb[idx] = kv;
    vb[idx] = vv;
}

// ---------------- rel-pos bias + causal mask, (h, i, j) ----------------
__global__ void bias_k(const float* __restrict__ emb, float* __restrict__ bias)
{
    size_t total = (size_t)Hn * Nn * NK1;
    size_t idx = (size_t)blockIdx.x * blockDim.x + threadIdx.x;
    if (idx >= total) return;
    int j = (int)(idx % NK1);
    size_t r = idx / NK1;
    int i = (int)(r % Nn);
    int h = (int)(r / Nn);
    float v;
    if (j > i + 1) {                 // causal: key token j-1 must be <= i
        v = -1e30f;
    } else {
        int n = i - j; if (n < 0) n = 0;
        int bucket;
        if (n < 16) bucket = n;
        else {
            float lf = logf((float)n * (1.f / 16.f)) * (16.f / logf(8.f));
            bucket = 16 + (int)lf;
            if (bucket > 31) bucket = 31;
        }
        v = emb[bucket * Hn + h];
    }
    bias[idx] = v;
}

// ---------------- swiglu: out = h * silu(gate) ----------------
__global__ void swiglu_k(const float* __restrict__ ff1, float* __restrict__ out)
{
    size_t total = (size_t)Bn * Nn * FIn;
    size_t idx = (size_t)blockIdx.x * blockDim.x + threadIdx.x;
    if (idx >= total) return;
    size_t row = idx / FIn;
    int c = (int)(idx - row * FIn);
    float h = ff1[row * (2 * FIn) + c];
    float gt = ff1[row * (2 * FIn) + FIn + c];
    out[idx] = h * (gt / (1.f + expf(-gt)));
}

// ---------------- host orchestration ----------------
static inline void gemm(const float* A, int lda, long aO, long aI,
                        const float* Bm, int ldb, long bO, long bI,
                        float* C, int ldc, long cO, long cI,
                        int M, int N, int K, int inner, int transB, int accum, int batches)
{
    dim3 gr(CDIV(N, GBN), CDIV(M, GBM), batches);
    gemm_k<<<gr, 256>>>(A, lda, aO, aI, Bm, ldb, bO, bI, C, ldc, cO, cI,
                        M, N, K, inner, transB, accum);
}

extern "C" void kernel_launch(void* const* d_in, const int* in_sizes, int n_in,
                              void* d_out, int out_size)
{
    (void)in_sizes; (void)n_in; (void)out_size;
    const float* in_x      = (const float*)d_in[0];
    const float* in_ctx    = (const float*)d_in[1];
    const float* in_relemb = (const float*)d_in[2];
    const float* in_sa_ng  = (const float*)d_in[3];
    const float* in_sa_wq  = (const float*)d_in[4];
    const float* in_sa_wkv = (const float*)d_in[5];
    const float* in_sa_nkv = (const float*)d_in[6];
    const float* in_sa_wo  = (const float*)d_in[7];
    const float* in_sa_og  = (const float*)d_in[8];
    const float* in_ca_ng  = (const float*)d_in[9];
    const float* in_ca_cg  = (const float*)d_in[10];
    const float* in_ca_wq  = (const float*)d_in[11];
    const float* in_ca_wkv = (const float*)d_in[12];
    const float* in_ca_nkv = (const float*)d_in[13];
    const float* in_ca_wo  = (const float*)d_in[14];
    const float* in_ca_og  = (const float*)d_in[15];
    const float* in_ff_ng  = (const float*)d_in[16];
    const float* in_ff_w1  = (const float*)d_in[17];
    const float* in_ff_w2  = (const float*)d_in[18];
    const float* in_norm_g = (const float*)d_in[19];
    float* out = (float*)d_out;

    float *px, *pxn, *pctxn, *pq, *pq2, *pkvt, *pk, *pv, *psim, *patt, *pproj, *pff1, *pffh, *pbias;
    cudaGetSymbolAddress((void**)&px,    g_x);
    cudaGetSymbolAddress((void**)&pxn,   g_xn);
    cudaGetSymbolAddress((void**)&pctxn, g_ctxn);
    cudaGetSymbolAddress((void**)&pq,    g_q);
    cudaGetSymbolAddress((void**)&pq2,   g_q2);
    cudaGetSymbolAddress((void**)&pkvt,  g_kvt);
    cudaGetSymbolAddress((void**)&pk,    g_k);
    cudaGetSymbolAddress((void**)&pv,    g_v);
    cudaGetSymbolAddress((void**)&psim,  g_sim);
    cudaGetSymbolAddress((void**)&patt,  g_att);
    cudaGetSymbolAddress((void**)&pproj, g_proj);
    cudaGetSymbolAddress((void**)&pff1,  g_ff1);
    cudaGetSymbolAddress((void**)&pffh,  g_ffh);
    cudaGetSymbolAddress((void**)&pbias, g_bias);

    const int rowsX = Bn * Nn;          // 4096
    const int rowsC = Bn * Mn;          // 2048
    const float scale = 0.125f;         // DH^-0.5

    cudaMemcpyAsync(px, in_x, sizeof(float) * (size_t)rowsX * Dn, cudaMemcpyDeviceToDevice);
    bias_k<<<CDIV((size_t)Hn * Nn * NK1, 256), 256>>>(in_relemb, pbias);

    for (int l = 0; l < Ln; l++) {
        const float* sa_ng  = in_sa_ng  + (size_t)l * Dn;
        const float* sa_wq  = in_sa_wq  + (size_t)l * Dn * Dn;
        const float* sa_wkv = in_sa_wkv + (size_t)l * Dn * 2 * DHn;
        const float* sa_nkv = in_sa_nkv + (size_t)l * 2 * DHn;
        const float* sa_wo  = in_sa_wo  + (size_t)l * Dn * Dn;
        const float* sa_og  = in_sa_og  + (size_t)l * Dn;
        const float* ca_ng  = in_ca_ng  + (size_t)l * Dn;
        const float* ca_cg  = in_ca_cg  + (size_t)l * Pn;
        const float* ca_wq  = in_ca_wq  + (size_t)l * Dn * Dn;
        const float* ca_wkv = in_ca_wkv + (size_t)l * Pn * 2 * DHn;
        const float* ca_nkv = in_ca_nkv + (size_t)l * 2 * DHn;
        const float* ca_wo  = in_ca_wo  + (size_t)l * Dn * Dn;
        const float* ca_og  = in_ca_og  + (size_t)l * Dn;
        const float* ff_ng  = in_ff_ng  + (size_t)l * Dn;
        const float* ff_w1  = in_ff_w1  + (size_t)l * Dn * 2 * FIn;
        const float* ff_w2  = in_ff_w2  + (size_t)l * FIn * Dn;

        // ===== self attention =====
        ln_k<<<rowsX, 256>>>(px, sa_ng, pxn, Dn);
        gemm(pxn, Dn, 0, 0, sa_wq, Dn, 0, 0, pq, Dn, 0, 0,
             rowsX, Hn * DHn, Dn, 1, 0, 0, 1);
        gemm(pxn, Dn, 0, 0, sa_wkv, 2 * DHn, 0, 0, pkvt, 2 * DHn, 0, 0,
             rowsX, 2 * DHn, Dn, 1, 0, 0, 1);
        rotq_k<<<CDIV((size_t)Bn * Nn * Hn * DHn, 256), 256>>>(pq, pq2);
        asmkv_k<<<CDIV((size_t)Bn * NK1 * DHn, 256), 256>>>(pkvt, sa_nkv, pk, pv, Nn, 1);
        // sim[b,h] = Q(b,h) @ K(b)^T
        gemm(pq2, Dn, (long)Nn * Dn, DHn,
             pk, DHn, (long)NK1 * DHn, 0,
             psim, NK1, (long)Hn * Nn * NK1, (long)Nn * NK1,
             Nn, NK1, DHn, Hn, 1, 0, Bn * Hn);
        softmax_k<<<Bn * Hn * Nn, 256>>>(psim, pbias, NK1, scale);
        // att[b, :, h, :] = P @ V(b)
        gemm(psim, NK1, (long)Hn * Nn * NK1, (long)Nn * NK1,
             pv, DHn, (long)NK1 * DHn, 0,
             patt, Dn, (long)Nn * Dn, DHn,
             Nn, DHn, NK1, Hn, 0, 0, Bn * Hn);
        gemm(patt, Dn, 0, 0, sa_wo, Dn, 0, 0, pproj, Dn, 0, 0,
             rowsX, Dn, Dn, 1, 0, 0, 1);
        lnadd_k<<<rowsX, 256>>>(pproj, sa_og, px, Dn);

        // ===== cross attention =====
        ln_k<<<rowsX, 256>>>(px, ca_ng, pxn, Dn);
        ln_k<<<rowsC, 256>>>(in_ctx, ca_cg, pctxn, Pn);
        gemm(pxn, Dn, 0, 0, ca_wq, Dn, 0, 0, pq, Dn, 0, 0,
             rowsX, Hn * DHn, Dn, 1, 0, 0, 1);
        gemm(pctxn, Pn, 0, 0, ca_wkv, 2 * DHn, 0, 0, pkvt, 2 * DHn, 0, 0,
             rowsC, 2 * DHn, Pn, 1, 0, 0, 1);
        asmkv_k<<<CDIV((size_t)Bn * NK2 * DHn, 256), 256>>>(pkvt, ca_nkv, pk, pv, Mn, 0);
        gemm(pq, Dn, (long)Nn * Dn, DHn,
             pk, DHn, (long)NK2 * DHn, 0,
             psim, NK2, (long)Hn * Nn * NK2, (long)Nn * NK2,
             Nn, NK2, DHn, Hn, 1, 0, Bn * Hn);
        softmax_k<<<Bn * Hn * Nn, 256>>>(psim, nullptr, NK2, scale);
        gemm(psim, NK2, (long)Hn * Nn * NK2, (long)Nn * NK2,
             pv, DHn, (long)NK2 * DHn, 0,
             patt, Dn, (long)Nn * Dn, DHn,
             Nn, DHn, NK2, Hn, 0, 0, Bn * Hn);
        gemm(patt, Dn, 0, 0, ca_wo, Dn, 0, 0, pproj, Dn, 0, 0,
             rowsX, Dn, Dn, 1, 0, 0, 1);
        lnadd_k<<<rowsX, 256>>>(pproj, ca_og, px, Dn);

        // ===== feed forward =====
        ln_k<<<rowsX, 256>>>(px, ff_ng, pxn, Dn);
        gemm(pxn, Dn, 0, 0, ff_w1, 2 * FIn, 0, 0, pff1, 2 * FIn, 0, 0,
             rowsX, 2 * FIn, Dn, 1, 0, 0, 1);
        swiglu_k<<<CDIV((size_t)Bn * Nn * FIn, 256), 256>>>(pff1, pffh);
        gemm(pffh, FIn, 0, 0, ff_w2, Dn, 0, 0, px, Dn, 0, 0,
             rowsX, Dn, FIn, 1, 0, 1, 1);   // accumulate residual directly
    }

    lnfinal_k<<<rowsX, 256>>>(px, in_norm_g, out);
}

// round 5
// speedup vs baseline: 2.1023x; 2.1023x over previous
#include <cuda_runtime.h>
#include <math.h>

// ---------------- problem constants ----------------
#define Bn 4
#define Nn 1024
#define Mn 512
#define Dn 512
#define Pn 256
#define Hn 8
#define DHn 64
#define Ln 6
#define FIn 2048
#define NK1 1025   // N + 1 (null kv)
#define NK2 513    // M + 1

#define CDIV(a,b) (((a)+(b)-1)/(b))

// ---------------- scratch (device globals; no allocation) ----------------
__device__ float g_x   [Bn*Nn*Dn];
__device__ float g_xn  [Bn*Nn*Dn];
__device__ float g_ctxn[Bn*Mn*Pn];
__device__ float g_q   [Bn*Nn*Hn*DHn];
__device__ float g_q2  [Bn*Nn*Hn*DHn];
__device__ float g_kvt [Bn*Nn*2*DHn];
__device__ float g_k   [Bn*NK1*DHn];
__device__ float g_v   [Bn*NK1*DHn];
__device__ float g_sim [(size_t)Bn*Hn*Nn*NK1];
__device__ float g_att [Bn*Nn*Hn*DHn];
__device__ float g_proj[Bn*Nn*Dn];
__device__ float g_ff1 [(size_t)Bn*Nn*2*FIn];
__device__ float g_ffh [(size_t)Bn*Nn*FIn];
__device__ float g_bias[(size_t)Hn*Nn*NK1];

// ---------------- reductions ----------------
__device__ __forceinline__ float warpSum(float v) {
    #pragma unroll
    for (int o = 16; o > 0; o >>= 1) v += __shfl_xor_sync(0xffffffffu, v, o);
    return v;
}
__device__ __forceinline__ float warpMax(float v) {
    #pragma unroll
    for (int o = 16; o > 0; o >>= 1) v = fmaxf(v, __shfl_xor_sync(0xffffffffu, v, o));
    return v;
}
__device__ float blockSum(float v) {
    __shared__ float sh[32];
    int lane = threadIdx.x & 31, w = threadIdx.x >> 5;
    int nw = blockDim.x >> 5;
    v = warpSum(v);
    __syncthreads();
    if (lane == 0) sh[w] = v;
    __syncthreads();
    float r = (lane < nw) ? sh[lane] : 0.f;
    return warpSum(r);
}
__device__ float blockMax(float v) {
    __shared__ float sh[32];
    int lane = threadIdx.x & 31, w = threadIdx.x >> 5;
    int nw = blockDim.x >> 5;
    v = warpMax(v);
    __syncthreads();
    if (lane == 0) sh[w] = v;
    __syncthreads();
    float r = (lane < nw) ? sh[lane] : -3.4e38f;
    return warpMax(r);
}

// =====================================================================
// tf32 tensor-core batched GEMM
// C[M,N] = A[M,K] @ B[K,N]   (TRANSB: B stored [N,K] row-major)
// block tile 128x128x16, 8 warps of 64x32, mma.sync.m16n8k8.tf32
// =====================================================================
#define BM 128
#define BN 128
#define BK 16
#define SA 20      // A/Bt smem row stride (conflict-free for frag loads)
#define SB 132     // B (no-trans) smem row stride

__device__ __forceinline__ unsigned f2tf(float f) {
    unsigned u; asm("cvt.rna.tf32.f32 %0, %1;" : "=r"(u) : "f"(f)); return u;
}

template<int TRANSB, int ACCUM>
__global__ void __launch_bounds__(256)
mma_gemm_k(const float* __restrict__ A, int lda, long aO, long aI,
           const float* __restrict__ Bm, int ldb, long bO, long bI,
           float* __restrict__ C, int ldc, long cO, long cI,
           int M, int N, int K, int inner)
{
    __shared__ float As[2][BM * SA];           // 2*2560 floats
    __shared__ float Bs[2][BM * SA];           // trans: [n][k] str20; no-trans: [k][n] str132 (2112<2560)

    int bz = blockIdx.z;
    int ob = bz / inner, ib = bz - ob * inner;
    A  += (size_t)ob * aO + (size_t)ib * aI;
    Bm += (size_t)ob * bO + (size_t)ib * bI;
    C  += (size_t)ob * cO + (size_t)ib * cI;

    int row0 = blockIdx.y * BM;
    int col0 = blockIdx.x * BN;
    int tid  = threadIdx.x;
    int lane = tid & 31, wid = tid >> 5;
    int wm = wid >> 2, wn = wid & 3;           // warp origin (wm*64, wn*32)
    int g  = lane >> 2, t4 = lane & 3;

    float acc[4][4][4];
    #pragma unroll
    for (int i = 0; i < 4; i++)
        #pragma unroll
        for (int j = 0; j < 4; j++)
            #pragma unroll
            for (int r = 0; r < 4; r++) acc[i][j][r] = 0.f;

    int T = (K + BK - 1) / BK;
    float ar[8], br[8];

    // ---- loaders (tile at k-offset k0) into registers ----
    auto loadA = [&](int k0) {
        #pragma unroll
        for (int i = 0; i < 2; i++) {
            int chunk = tid + i * 256;
            int r = chunk >> 2, kc = (chunk & 3) * 4;
            int gr = row0 + r;
            long base = (long)gr * lda + k0 + kc;
            if (gr < M && (k0 + kc + 3) < K && ((((size_t)(A + base)) & 15) == 0)) {
                float4 v = *(const float4*)(A + base);
                ar[i*4+0] = v.x; ar[i*4+1] = v.y; ar[i*4+2] = v.z; ar[i*4+3] = v.w;
            } else {
                #pragma unroll
                for (int j = 0; j < 4; j++)
                    ar[i*4+j] = (gr < M && (k0 + kc + j) < K) ? A[base + j] : 0.f;
            }
        }
    };
    auto loadB = [&](int k0) {
        if (!TRANSB) {
            #pragma unroll
            for (int i = 0; i < 2; i++) {
                int chunk = tid + i * 256;
                int kr = chunk >> 5, nc = (chunk & 31) * 4;
                int gk = k0 + kr, gn0 = col0 + nc;
                long base = (long)gk * ldb + gn0;
                if (gk < K && (gn0 + 3) < N && ((((size_t)(Bm + base)) & 15) == 0)) {
                    float4 v = *(const float4*)(Bm + base);
                    br[i*4+0] = v.x; br[i*4+1] = v.y; br[i*4+2] = v.z; br[i*4+3] = v.w;
                } else {
                    #pragma unroll
                    for (int j = 0; j < 4; j++)
                        br[i*4+j] = (gk < K && (gn0 + j) < N) ? Bm[base + j] : 0.f;
                }
            }
        } else {
            #pragma unroll
            for (int i = 0; i < 2; i++) {
                int chunk = tid + i * 256;
                int nr = chunk >> 2, kc = (chunk & 3) * 4;
                int gn = col0 + nr, gk0 = k0 + kc;
                long base = (long)gn * ldb + gk0;
                if (gn < N && (gk0 + 3) < K && ((((size_t)(Bm + base)) & 15) == 0)) {
                    float4 v = *(const float4*)(Bm + base);
                    br[i*4+0] = v.x; br[i*4+1] = v.y; br[i*4+2] = v.z; br[i*4+3] = v.w;
                } else {
                    #pragma unroll
                    for (int j = 0; j < 4; j++)
                        br[i*4+j] = (gn < N && (gk0 + j) < K) ? Bm[base + j] : 0.f;
                }
            }
        }
    };
    auto store = [&](int buf) {
        #pragma unroll
        for (int i = 0; i < 2; i++) {
            int chunk = tid + i * 256;
            int r = chunk >> 2, kc = (chunk & 3) * 4;
            float4 v;
            v.x = __uint_as_float(f2tf(ar[i*4+0]));
            v.y = __uint_as_float(f2tf(ar[i*4+1]));
            v.z = __uint_as_float(f2tf(ar[i*4+2]));
            v.w = __uint_as_float(f2tf(ar[i*4+3]));
            *(float4*)&As[buf][r * SA + kc] = v;
        }
        if (!TRANSB) {
            #pragma unroll
            for (int i = 0; i < 2; i++) {
                int chunk = tid + i * 256;
                int kr = chunk >> 5, nc = (chunk & 31) * 4;
                float4 v;
                v.x = __uint_as_float(f2tf(br[i*4+0]));
                v.y = __uint_as_float(f2tf(br[i*4+1]));
                v.z = __uint_as_float(f2tf(br[i*4+2]));
                v.w = __uint_as_float(f2tf(br[i*4+3]));
                *(float4*)&Bs[buf][kr * SB + nc] = v;
            }
        } else {
            #pragma unroll
            for (int i = 0; i < 2; i++) {
                int chunk = tid + i * 256;
                int nr = chunk >> 2, kc = (chunk & 3) * 4;
                float4 v;
                v.x = __uint_as_float(f2tf(br[i*4+0]));
                v.y = __uint_as_float(f2tf(br[i*4+1]));
                v.z = __uint_as_float(f2tf(br[i*4+2]));
                v.w = __uint_as_float(f2tf(br[i*4+3]));
                *(float4*)&Bs[buf][nr * SA + kc] = v;
            }
        }
    };
    auto compute = [&](int buf) {
        #pragma unroll
        for (int ks = 0; ks < 2; ks++) {
            int k0 = ks * 8;
            unsigned af[4][4], bf[4][2];
            #pragma unroll
            for (int mi = 0; mi < 4; mi++) {
                int r = wm * 64 + mi * 16 + g;
                af[mi][0] = __float_as_uint(As[buf][(r    ) * SA + k0 + t4    ]);
                af[mi][1] = __float_as_uint(As[buf][(r + 8) * SA + k0 + t4    ]);
                af[mi][2] = __float_as_uint(As[buf][(r    ) * SA + k0 + t4 + 4]);
                af[mi][3] = __float_as_uint(As[buf][(r + 8) * SA + k0 + t4 + 4]);
            }
            #pragma unroll
            for (int ni = 0; ni < 4; ni++) {
                int n = wn * 32 + ni * 8 + g;
                if (!TRANSB) {
                    bf[ni][0] = __float_as_uint(Bs[buf][(k0 + t4    ) * SB + n]);
                    bf[ni][1] = __float_as_uint(Bs[buf][(k0 + t4 + 4) * SB + n]);
                } else {
                    bf[ni][0] = __float_as_uint(Bs[buf][n * SA + k0 + t4    ]);
                    bf[ni][1] = __float_as_uint(Bs[buf][n * SA + k0 + t4 + 4]);
                }
            }
            #pragma unroll
            for (int mi = 0; mi < 4; mi++)
                #pragma unroll
                for (int ni = 0; ni < 4; ni++) {
                    asm volatile(
                        "mma.sync.aligned.m16n8k8.row.col.f32.tf32.tf32.f32 "
                        "{%0,%1,%2,%3}, {%4,%5,%6,%7}, {%8,%9}, {%0,%1,%2,%3};"
                        : "+f"(acc[mi][ni][0]), "+f"(acc[mi][ni][1]),
                          "+f"(acc[mi][ni][2]), "+f"(acc[mi][ni][3])
                        : "r"(af[mi][0]), "r"(af[mi][1]), "r"(af[mi][2]), "r"(af[mi][3]),
                          "r"(bf[ni][0]), "r"(bf[ni][1]));
                }
        }
    };

    // ---- pipeline ----
    loadA(0); loadB(0); store(0);
    __syncthreads();
    for (int t = 0; t < T; t++) {
        int buf = t & 1;
        if (t + 1 < T) { loadA((t + 1) * BK); loadB((t + 1) * BK); }
        compute(buf);
        __syncthreads();
        if (t + 1 < T) {
            store(buf ^ 1);
        }
        __syncthreads();
    }

    // ---- epilogue ----
    #pragma unroll
    for (int mi = 0; mi < 4; mi++) {
        #pragma unroll
        for (int ni = 0; ni < 4; ni++) {
            int r_ = row0 + wm * 64 + mi * 16 + g;
            int c_ = col0 + wn * 32 + ni * 8 + t4 * 2;
            if (r_ < M) {
                size_t o0 = (size_t)r_ * ldc + c_;
                if (c_ < N)     { if (ACCUM) C[o0]     += acc[mi][ni][0]; else C[o0]     = acc[mi][ni][0]; }
                if (c_ + 1 < N) { if (ACCUM) C[o0 + 1] += acc[mi][ni][1]; else C[o0 + 1] = acc[mi][ni][1]; }
            }
            if (r_ + 8 < M) {
                size_t o2 = (size_t)(r_ + 8) * ldc + c_;
                if (c_ < N)     { if (ACCUM) C[o2]     += acc[mi][ni][2]; else C[o2]     = acc[mi][ni][2]; }
                if (c_ + 1 < N) { if (ACCUM) C[o2 + 1] += acc[mi][ni][3]; else C[o2 + 1] = acc[mi][ni][3]; }
            }
        }
    }
}

// ---------------- layernorm (one block per row) ----------------
__global__ void ln_k(const float* __restrict__ x, const float* __restrict__ g,
                     float* __restrict__ out, int C)
{
    size_t row = blockIdx.x;
    const float* xr = x + row * C;
    float s = 0.f;
    for (int c = threadIdx.x; c < C; c += blockDim.x) s += xr[c];
    float mu = blockSum(s) / C;
    float v = 0.f;
    for (int c = threadIdx.x; c < C; c += blockDim.x) { float d = xr[c] - mu; v += d * d; }
    float rstd = rsqrtf(blockSum(v) / C + 1e-5f);
    float* orow = out + row * C;
    for (int c = threadIdx.x; c < C; c += blockDim.x) orow[c] = (xr[c] - mu) * rstd * g[c];
}

__global__ void lnadd_k(const float* __restrict__ p, const float* __restrict__ g,
                        float* __restrict__ x, int C)
{
    size_t row = blockIdx.x;
    const float* pr = p + row * C;
    float s = 0.f;
    for (int c = threadIdx.x; c < C; c += blockDim.x) s += pr[c];
    float mu = blockSum(s) / C;
    float v = 0.f;
    for (int c = threadIdx.x; c < C; c += blockDim.x) { float d = pr[c] - mu; v += d * d; }
    float rstd = rsqrtf(blockSum(v) / C + 1e-5f);
    float* xr = x + row * C;
    for (int c = threadIdx.x; c < C; c += blockDim.x) xr[c] += (pr[c] - mu) * rstd * g[c];
}

__global__ void lnfinal_k(const float* __restrict__ x, const float* __restrict__ g,
                          float* __restrict__ out)
{
    const int C = Dn;
    size_t row = blockIdx.x;
    const float* xr = x + row * C;
    float m = -3.4e38f;
    for (int c = threadIdx.x; c < C; c += blockDim.x) m = fmaxf(m, xr[c]);
    m = blockMax(m);
    float inv = 1.f / m;
    float s = 0.f;
    for (int c = threadIdx.x; c < C; c += blockDim.x) s += xr[c] * inv;
    float mu = blockSum(s) / C;
    float v = 0.f;
    for (int c = threadIdx.x; c < C; c += blockDim.x) { float d = xr[c] * inv - mu; v += d * d; }
    float rstd = rsqrtf(blockSum(v) / C + 1e-5f);
    float* orow = out + row * C;
    for (int c = threadIdx.x; c < C; c += blockDim.x) orow[c] = (xr[c] * inv - mu) * rstd * g[c];
}

// ---------------- softmax ----------------
__global__ void softmax_k(float* __restrict__ sim, const float* __restrict__ bias,
                          int Nk, float scale)
{
    size_t row = blockIdx.x;
    float* sr = sim + row * (size_t)Nk;
    const float* br = nullptr;
    if (bias) {
        int i = (int)(row % Nn);
        int h = (int)((row / Nn) % Hn);
        br = bias + ((size_t)h * Nn + i) * (size_t)Nk;
    }
    float mx = -3.4e38f;
    for (int j = threadIdx.x; j < Nk; j += blockDim.x) {
        float v = sr[j] * scale + (br ? br[j] : 0.f);
        sr[j] = v;
        mx = fmaxf(mx, v);
    }
    mx = blockMax(mx);
    float s = 0.f;
    for (int j = threadIdx.x; j < Nk; j += blockDim.x) {
        float e = expf(sr[j] - mx);
        sr[j] = e;
        s += e;
    }
    s = blockSum(s);
    float inv = 1.f / s;
    for (int j = threadIdx.x; j < Nk; j += blockDim.x) sr[j] *= inv;
}

// ---------------- rotary on q ----------------
__global__ void rotq_k(const float* __restrict__ q, float* __restrict__ o)
{
    size_t idx = (size_t)blockIdx.x * blockDim.x + threadIdx.x;
    if (idx >= (size_t)Bn * Nn * Hn * DHn) return;
    int c = (int)(idx & 63);
    float val = q[idx];
    if (c < 32) {
        int n = (int)((idx >> 9) & (Nn - 1));
        int p = c & 15;
        float invf = powf(10000.f, -(float)p / 16.f);
        float f = (float)n * invf;
        float partner = (c < 16) ? q[idx + 16] : q[idx - 16];
        val = val * cosf(f) + ((c < 16) ? -partner : partner) * sinf(f);
    }
    o[idx] = val;
}

// ---------------- assemble K/V ----------------
__global__ void asmkv_k(const float* __restrict__ kvt, const float* __restrict__ nkv,
                        float* __restrict__ kb, float* __restrict__ vb,
                        int Nsrc, int useRot)
{
    int NkL = Nsrc + 1;
    size_t total = (size_t)Bn * NkL * DHn;
    size_t idx = (size_t)blockIdx.x * blockDim.x + threadIdx.x;
    if (idx >= total) return;
    int c = (int)(idx & 63);
    size_t bj = idx >> 6;
    int j = (int)(bj % NkL);
    float kv, vv;
    if (j == 0) {
        kv = nkv[c];
        vv = nkv[DHn + c];
    } else {
        const float* rp = kvt + ((bj / NkL) * Nsrc + (j - 1)) * (size_t)(2 * DHn);
        kv = rp[c];
        vv = rp[DHn + c];
        if (useRot && c < 32) {
            int p = c & 15;
            float invf = powf(10000.f, -(float)p / 16.f);
            float f = (float)(j - 1) * invf;
            float partner = (c < 16) ? rp[c + 16] : rp[c - 16];
            kv = kv * cosf(f) + ((c < 16) ? -partner : partner) * sinf(f);
        }
    }
    kb[idx] = kv;
    vb[idx] = vv;
}

// ---------------- rel-pos bias + causal mask ----------------
__global__ void bias_k(const float* __restrict__ emb, float* __restrict__ bias)
{
    size_t total = (size_t)Hn * Nn * NK1;
    size_t idx = (size_t)blockIdx.x * blockDim.x + threadIdx.x;
    if (idx >= total) return;
    int j = (int)(idx % NK1);
    size_t r = idx / NK1;
    int i = (int)(r % Nn);
    int h = (int)(r / Nn);
    float v;
    if (j > i + 1) {
        v = -1e30f;
    } else {
        int n = i - j; if (n < 0) n = 0;
        int bucket;
        if (n < 16) bucket = n;
        else {
            float lf = logf((float)n * (1.f / 16.f)) * (16.f / logf(8.f));
            bucket = 16 + (int)lf;
            if (bucket > 31) bucket = 31;
        }
        v = emb[bucket * Hn + h];
    }
    bias[idx] = v;
}

// ---------------- swiglu ----------------
__global__ void swiglu_k(const float* __restrict__ ff1, float* __restrict__ out)
{
    size_t total = (size_t)Bn * Nn * FIn;
    size_t idx = (size_t)blockIdx.x * blockDim.x + threadIdx.x;
    if (idx >= total) return;
    size_t row = idx / FIn;
    int c = (int)(idx - row * FIn);
    float h = ff1[row * (2 * FIn) + c];
    float gt = ff1[row * (2 * FIn) + FIn + c];
    out[idx] = h * (gt / (1.f + expf(-gt)));
}

// ---------------- host orchestration ----------------
static inline void gemm(const float* A, int lda, long aO, long aI,
                        const float* Bm, int ldb, long bO, long bI,
                        float* C, int ldc, long cO, long cI,
                        int M, int N, int K, int inner, int transB, int accum, int batches)
{
    dim3 gr(CDIV(N, BN), CDIV(M, BM), batches);
    if (transB) {
        if (accum) mma_gemm_k<1,1><<<gr, 256>>>(A, lda, aO, aI, Bm, ldb, bO, bI, C, ldc, cO, cI, M, N, K, inner);
        else       mma_gemm_k<1,0><<<gr, 256>>>(A, lda, aO, aI, Bm, ldb, bO, bI, C, ldc, cO, cI, M, N, K, inner);
    } else {
        if (accum) mma_gemm_k<0,1><<<gr, 256>>>(A, lda, aO, aI, Bm, ldb, bO, bI, C, ldc, cO, cI, M, N, K, inner);
        else       mma_gemm_k<0,0><<<gr, 256>>>(A, lda, aO, aI, Bm, ldb, bO, bI, C, ldc, cO, cI, M, N, K, inner);
    }
}

extern "C" void kernel_launch(void* const* d_in, const int* in_sizes, int n_in,
                              void* d_out, int out_size)
{
    (void)in_sizes; (void)n_in; (void)out_size;
    const float* in_x      = (const float*)d_in[0];
    const float* in_ctx    = (const float*)d_in[1];
    const float* in_relemb = (const float*)d_in[2];
    const float* in_sa_ng  = (const float*)d_in[3];
    const float* in_sa_wq  = (const float*)d_in[4];
    const float* in_sa_wkv = (const float*)d_in[5];
    const float* in_sa_nkv = (const float*)d_in[6];
    const float* in_sa_wo  = (const float*)d_in[7];
    const float* in_sa_og  = (const float*)d_in[8];
    const float* in_ca_ng  = (const float*)d_in[9];
    const float* in_ca_cg  = (const float*)d_in[10];
    const float* in_ca_wq  = (const float*)d_in[11];
    const float* in_ca_wkv = (const float*)d_in[12];
    const float* in_ca_nkv = (const float*)d_in[13];
    const float* in_ca_wo  = (const float*)d_in[14];
    const float* in_ca_og  = (const float*)d_in[15];
    const float* in_ff_ng  = (const float*)d_in[16];
    const float* in_ff_w1  = (const float*)d_in[17];
    const float* in_ff_w2  = (const float*)d_in[18];
    const float* in_norm_g = (const float*)d_in[19];
    float* out = (float*)d_out;

    float *px, *pxn, *pctxn, *pq, *pq2, *pkvt, *pk, *pv, *psim, *patt, *pproj, *pff1, *pffh, *pbias;
    cudaGetSymbolAddress((void**)&px,    g_x);
    cudaGetSymbolAddress((void**)&pxn,   g_xn);
    cudaGetSymbolAddress((void**)&pctxn, g_ctxn);
    cudaGetSymbolAddress((void**)&pq,    g_q);
    cudaGetSymbolAddress((void**)&pq2,   g_q2);
    cudaGetSymbolAddress((void**)&pkvt,  g_kvt);
    cudaGetSymbolAddress((void**)&pk,    g_k);
    cudaGetSymbolAddress((void**)&pv,    g_v);
    cudaGetSymbolAddress((void**)&psim,  g_sim);
    cudaGetSymbolAddress((void**)&patt,  g_att);
    cudaGetSymbolAddress((void**)&pproj, g_proj);
    cudaGetSymbolAddress((void**)&pff1,  g_ff1);
    cudaGetSymbolAddress((void**)&pffh,  g_ffh);
    cudaGetSymbolAddress((void**)&pbias, g_bias);

    const int rowsX = Bn * Nn;
    const int rowsC = Bn * Mn;
    const float scale = 0.125f;

    cudaMemcpyAsync(px, in_x, sizeof(float) * (size_t)rowsX * Dn, cudaMemcpyDeviceToDevice);
    bias_k<<<CDIV((size_t)Hn * Nn * NK1, 256), 256>>>(in_relemb, pbias);

    for (int l = 0; l < Ln; l++) {
        const float* sa_ng  = in_sa_ng  + (size_t)l * Dn;
        const float* sa_wq  = in_sa_wq  + (size_t)l * Dn * Dn;
        const float* sa_wkv = in_sa_wkv + (size_t)l * Dn * 2 * DHn;
        const float* sa_nkv = in_sa_nkv + (size_t)l * 2 * DHn;
        const float* sa_wo  = in_sa_wo  + (size_t)l * Dn * Dn;
        const float* sa_og  = in_sa_og  + (size_t)l * Dn;
        const float* ca_ng  = in_ca_ng  + (size_t)l * Dn;
        const float* ca_cg  = in_ca_cg  + (size_t)l * Pn;
        const float* ca_wq  = in_ca_wq  + (size_t)l * Dn * Dn;
        const float* ca_wkv = in_ca_wkv + (size_t)l * Pn * 2 * DHn;
        const float* ca_nkv = in_ca_nkv + (size_t)l * 2 * DHn;
        const float* ca_wo  = in_ca_wo  + (size_t)l * Dn * Dn;
        const float* ca_og  = in_ca_og  + (size_t)l * Dn;
        const float* ff_ng  = in_ff_ng  + (size_t)l * Dn;
        const float* ff_w1  = in_ff_w1  + (size_t)l * Dn * 2 * FIn;
        const float* ff_w2  = in_ff_w2  + (size_t)l * FIn * Dn;

        // ===== self attention =====
        ln_k<<<rowsX, 256>>>(px, sa_ng, pxn, Dn);
        gemm(pxn, Dn, 0, 0, sa_wq, Dn, 0, 0, pq, Dn, 0, 0,
             rowsX, Hn * DHn, Dn, 1, 0, 0, 1);
        gemm(pxn, Dn, 0, 0, sa_wkv, 2 * DHn, 0, 0, pkvt, 2 * DHn, 0, 0,
             rowsX, 2 * DHn, Dn, 1, 0, 0, 1);
        rotq_k<<<CDIV((size_t)Bn * Nn * Hn * DHn, 256), 256>>>(pq, pq2);
        asmkv_k<<<CDIV((size_t)Bn * NK1 * DHn, 256), 256>>>(pkvt, sa_nkv, pk, pv, Nn, 1);
        gemm(pq2, Dn, (long)Nn * Dn, DHn,
             pk, DHn, (long)NK1 * DHn, 0,
             psim, NK1, (long)Hn * Nn * NK1, (long)Nn * NK1,
             Nn, NK1, DHn, Hn, 1, 0, Bn * Hn);
        softmax_k<<<Bn * Hn * Nn, 256>>>(psim, pbias, NK1, scale);
        gemm(psim, NK1, (long)Hn * Nn * NK1, (long)Nn * NK1,
             pv, DHn, (long)NK1 * DHn, 0,
             patt, Dn, (long)Nn * Dn, DHn,
             Nn, DHn, NK1, Hn, 0, 0, Bn * Hn);
        gemm(patt, Dn, 0, 0, sa_wo, Dn, 0, 0, pproj, Dn, 0, 0,
             rowsX, Dn, Dn, 1, 0, 0, 1);
        lnadd_k<<<rowsX, 256>>>(pproj, sa_og, px, Dn);

        // ===== cross attention =====
        ln_k<<<rowsX, 256>>>(px, ca_ng, pxn, Dn);
        ln_k<<<rowsC, 256>>>(in_ctx, ca_cg, pctxn, Pn);
        gemm(pxn, Dn, 0, 0, ca_wq, Dn, 0, 0, pq, Dn, 0, 0,
             rowsX, Hn * DHn, Dn, 1, 0, 0, 1);
        gemm(pctxn, Pn, 0, 0, ca_wkv, 2 * DHn, 0, 0, pkvt, 2 * DHn, 0, 0,
             rowsC, 2 * DHn, Pn, 1, 0, 0, 1);
        asmkv_k<<<CDIV((size_t)Bn * NK2 * DHn, 256), 256>>>(pkvt, ca_nkv, pk, pv, Mn, 0);
        gemm(pq, Dn, (long)Nn * Dn, DHn,
             pk, DHn, (long)NK2 * DHn, 0,
             psim, NK2, (long)Hn * Nn * NK2, (long)Nn * NK2,
             Nn, NK2, DHn, Hn, 1, 0, Bn * Hn);
        softmax_k<<<Bn * Hn * Nn, 256>>>(psim, nullptr, NK2, scale);
        gemm(psim, NK2, (long)Hn * Nn * NK2, (long)Nn * NK2,
             pv, DHn, (long)NK1 * DHn * 0 + (long)NK2 * DHn, 0,
             patt, Dn, (long)Nn * Dn, DHn,
             Nn, DHn, NK2, Hn, 0, 0, Bn * Hn);
        gemm(patt, Dn, 0, 0, ca_wo, Dn, 0, 0, pproj, Dn, 0, 0,
             rowsX, Dn, Dn, 1, 0, 0, 1);
        lnadd_k<<<rowsX, 256>>>(pproj, ca_og, px, Dn);

        // ===== feed forward =====
        ln_k<<<rowsX, 256>>>(px, ff_ng, pxn, Dn);
        gemm(pxn, Dn, 0, 0, ff_w1, 2 * FIn, 0, 0, pff1, 2 * FIn, 0, 0,
             rowsX, 2 * FIn, Dn, 1, 0, 0, 1);
        swiglu_k<<<CDIV((size_t)Bn * Nn * FIn, 256), 256>>>(pff1, pffh);
        gemm(pffh, FIn, 0, 0, ff_w2, Dn, 0, 0, px, Dn, 0, 0,
             rowsX, Dn, FIn, 1, 0, 1, 1);
    }

    lnfinal_k<<<rowsX, 256>>>(px, in_norm_g, out);
}

// round 10
// speedup vs baseline: 3.3552x; 1.5959x over previous
#include <cuda_runtime.h>
#include <stdint.h>
#include <stddef.h>
#include <math.h>

// ---------------- problem constants ----------------
#define Bn 4
#define Nn 1024
#define Mn 512
#define Dn 512
#define Pn 256
#define Hn 8
#define DHn 64
#define Ln 6
#define FIn 2048
#define NK1 1025   // N + 1 (null kv)
#define NK2 513    // M + 1

#define CDIV(a,b) (((a)+(b)-1)/(b))

// ---------------- scratch (device globals; no allocation) ----------------
__device__ float g_x   [Bn*Nn*Dn];
__device__ float g_xn  [Bn*Nn*Dn];
__device__ float g_ctxn[Bn*Mn*Pn];
__device__ float g_q   [Bn*Nn*Hn*DHn];
__device__ float g_q2  [Bn*Nn*Hn*DHn];
__device__ float g_kvt [Bn*Nn*2*DHn];
__device__ float g_k   [Bn*NK1*DHn];
__device__ float g_v   [Bn*NK1*DHn];
__device__ float g_att [Bn*Nn*Hn*DHn];
__device__ float g_proj[Bn*Nn*Dn];
__device__ float g_ff1 [(size_t)Bn*Nn*2*FIn];
__device__ float g_ffh [(size_t)Bn*Nn*FIn];
__device__ float g_bias[(size_t)Hn*Nn*NK1];

// ---------------- reductions ----------------
__device__ __forceinline__ float warpSum(float v) {
    #pragma unroll
    for (int o = 16; o > 0; o >>= 1) v += __shfl_xor_sync(0xffffffffu, v, o);
    return v;
}
__device__ __forceinline__ float warpMax(float v) {
    #pragma unroll
    for (int o = 16; o > 0; o >>= 1) v = fmaxf(v, __shfl_xor_sync(0xffffffffu, v, o));
    return v;
}
__device__ float blockSum(float v) {
    __shared__ float sh[32];
    int lane = threadIdx.x & 31, w = threadIdx.x >> 5;
    int nw = blockDim.x >> 5;
    v = warpSum(v);
    __syncthreads();
    if (lane == 0) sh[w] = v;
    __syncthreads();
    float r = (lane < nw) ? sh[lane] : 0.f;
    return warpSum(r);
}
__device__ float blockMax(float v) {
    __shared__ float sh[32];
    int lane = threadIdx.x & 31, w = threadIdx.x >> 5;
    int nw = blockDim.x >> 5;
    v = warpMax(v);
    __syncthreads();
    if (lane == 0) sh[w] = v;
    __syncthreads();
    float r = (lane < nw) ? sh[lane] : -3.4e38f;
    return warpMax(r);
}

__device__ __forceinline__ unsigned f2tf(float f) {
    unsigned u; asm("cvt.rna.tf32.f32 %0, %1;" : "=r"(u) : "f"(f)); return u;
}

#define MMA_TF32(ACC, AF, BF) \
    asm volatile( \
        "mma.sync.aligned.m16n8k8.row.col.f32.tf32.tf32.f32 " \
        "{%0,%1,%2,%3}, {%4,%5,%6,%7}, {%8,%9}, {%0,%1,%2,%3};" \
        : "+f"((ACC)[0]), "+f"((ACC)[1]), "+f"((ACC)[2]), "+f"((ACC)[3]) \
        : "r"((AF)[0]), "r"((AF)[1]), "r"((AF)[2]), "r"((AF)[3]), \
          "r"((BF)[0]), "r"((BF)[1]))

// =====================================================================
// Pipelined tf32 GEMM: C[M,N] = A[M,K] @ B[K,N], all row-major,
// lda=K, ldb=N, ldc=N; M%128==0, N%128==0, K%16==0.
// 4-stage cp.async, 128x128x16 tile, 8 warps of 64x32.
// =====================================================================
#define GS 4
#define SA 20
#define SB 132
#define STAGEF (128*SA + 16*SB)   // floats per stage

__device__ __forceinline__ void cp16(uint32_t s, const float* g) {
    asm volatile("cp.async.ca.shared.global [%0], [%1], 16;" :: "r"(s), "l"(g));
}

template<int ACCUM>
__global__ void __launch_bounds__(256)
gemm2_k(const float* __restrict__ A, const float* __restrict__ B,
        float* __restrict__ C, int M, int N, int K)
{
    extern __shared__ float sm[];
    int row0 = blockIdx.y * 128, col0 = blockIdx.x * 128;
    int tid = threadIdx.x, lane = tid & 31, wid = tid >> 5;
    int wm = wid >> 2, wn = wid & 3, g = lane >> 2, t4 = lane & 3;
    int T = K >> 4;

    auto loadTile = [&](int t) {
        int k0 = t << 4;
        float* As = sm + (t % GS) * STAGEF;
        float* Bs = As + 128 * SA;
        uint32_t asu = (uint32_t)__cvta_generic_to_shared(As);
        uint32_t bsu = (uint32_t)__cvta_generic_to_shared(Bs);
        #pragma unroll
        for (int i = 0; i < 2; i++) {
            int ch = tid + i * 256;
            int r = ch >> 2, kc = (ch & 3) * 4;
            cp16(asu + (r * SA + kc) * 4, A + (size_t)(row0 + r) * K + k0 + kc);
        }
        #pragma unroll
        for (int i = 0; i < 2; i++) {
            int ch = tid + i * 256;
            int kr = ch >> 5, nc = (ch & 31) * 4;
            cp16(bsu + (kr * SB + nc) * 4, B + (size_t)(k0 + kr) * N + col0 + nc);
        }
    };

    float acc[4][4][4] = {};

    #pragma unroll
    for (int s = 0; s < GS - 1; s++) {
        if (s < T) loadTile(s);
        asm volatile("cp.async.commit_group;");
    }

    for (int t = 0; t < T; t++) {
        asm volatile("cp.async.wait_group %0;" :: "n"(GS - 2));
        __syncthreads();
        int nt = t + GS - 1;
        if (nt < T) loadTile(nt);
        asm volatile("cp.async.commit_group;");

        const float* As = sm + (t % GS) * STAGEF;
        const float* Bs = As + 128 * SA;
        #pragma unroll
        for (int ks = 0; ks < 2; ks++) {
            int k0 = ks * 8;
            unsigned af[4][4], bf[4][2];
            #pragma unroll
            for (int mi = 0; mi < 4; mi++) {
                int r = wm * 64 + mi * 16 + g;
                af[mi][0] = f2tf(As[(r    ) * SA + k0 + t4    ]);
                af[mi][1] = f2tf(As[(r + 8) * SA + k0 + t4    ]);
                af[mi][2] = f2tf(As[(r    ) * SA + k0 + t4 + 4]);
                af[mi][3] = f2tf(As[(r + 8) * SA + k0 + t4 + 4]);
            }
            #pragma unroll
            for (int ni = 0; ni < 4; ni++) {
                int n = wn * 32 + ni * 8 + g;
                bf[ni][0] = f2tf(Bs[(k0 + t4    ) * SB + n]);
                bf[ni][1] = f2tf(Bs[(k0 + t4 + 4) * SB + n]);
            }
            #pragma unroll
            for (int mi = 0; mi < 4; mi++)
                #pragma unroll
                for (int ni = 0; ni < 4; ni++)
                    MMA_TF32(acc[mi][ni], af[mi], bf[ni]);
        }
    }

    #pragma unroll
    for (int mi = 0; mi < 4; mi++) {
        int r_ = row0 + wm * 64 + mi * 16 + g;
        #pragma unroll
        for (int ni = 0; ni < 4; ni++) {
            int c_ = col0 + wn * 32 + ni * 8 + t4 * 2;
            size_t o0 = (size_t)r_ * N + c_;
            size_t o2 = (size_t)(r_ + 8) * N + c_;
            if (ACCUM) {
                C[o0]     += acc[mi][ni][0];
                C[o0 + 1] += acc[mi][ni][1];
                C[o2]     += acc[mi][ni][2];
                C[o2 + 1] += acc[mi][ni][3];
            } else {
                C[o0]     = acc[mi][ni][0];
                C[o0 + 1] = acc[mi][ni][1];
                C[o2]     = acc[mi][ni][2];
                C[o2 + 1] = acc[mi][ni][3];
            }
        }
    }
}

// =====================================================================
// Flash attention: one block per (q-tile of 128, b*H).
// Q (b,n,h,64), K/V (b, Nk, 64). S tile 128x128 via mma, online softmax,
// P routed through smem, O accumulated in registers.
// CAUSAL=1: adds precomputed bias table (contains causal mask) and
// processes only qt+2 kv tiles.
// =====================================================================
#define FQS 68
#define FPS 132
#define FSM_K (128*FQS)
#define FSM_V (2*128*FQS)
#define FSM_P (3*128*FQS)
#define FSM_RS (FSM_P + 128*FPS)
#define FSM_RL (FSM_RS + 128)
#define FSM_TOT (FSM_RL + 128)

template<int CAUSAL>
__global__ void __launch_bounds__(256)
flash_k(const float* __restrict__ Qp, const float* __restrict__ Kp,
        const float* __restrict__ Vp, const float* __restrict__ bias,
        float* __restrict__ Op, int Nk)
{
    extern __shared__ float sm[];
    float* Qs = sm;
    float* Ks = sm + FSM_K;
    float* Vs = sm + FSM_V;
    float* Ps = sm + FSM_P;
    float* rowScale = sm + FSM_RS;
    float* rowSum   = sm + FSM_RL;

    const float scale = 0.125f;
    int qt = blockIdx.x, bh = blockIdx.y;
    int b = bh >> 3, h = bh & 7;
    int tid = threadIdx.x, lane = tid & 31, wid = tid >> 5;
    int wm = wid >> 2, wn = wid & 3, g = lane >> 2, t4 = lane & 3;
    int i0 = qt * 128;
    int nT = CAUSAL ? (qt + 2) : CDIV(Nk, 128);

    // load Q tile (128 x 64)
    #pragma unroll
    for (int c = tid; c < 128 * 16; c += 256) {
        int r = c >> 4, dc = (c & 15) * 4;
        float4 v = *(const float4*)(Qp + (((size_t)(b * Nn + i0 + r)) * Hn + h) * DHn + dc);
        *(float4*)&Qs[r * FQS + dc] = v;
    }

    float m_st[16], l_st[16];
    #pragma unroll
    for (int jr = 0; jr < 16; jr++) { m_st[jr] = -3.0e38f; l_st[jr] = 0.f; }
    float acc_o[4][2][4] = {};

    for (int t = 0; t < nT; t++) {
        int j0 = t * 128;
        // load K/V tile (zero-fill beyond Nk)
        #pragma unroll
        for (int c = tid; c < 128 * 16; c += 256) {
            int r = c >> 4, dc = (c & 15) * 4;
            int j = j0 + r;
            float4 kv = {0.f,0.f,0.f,0.f}, vv = {0.f,0.f,0.f,0.f};
            if (j < Nk) {
                kv = *(const float4*)(Kp + ((size_t)b * Nk + j) * DHn + dc);
                vv = *(const float4*)(Vp + ((size_t)b * Nk + j) * DHn + dc);
            }
            *(float4*)&Ks[r * FQS + dc] = kv;
            *(float4*)&Vs[r * FQS + dc] = vv;
        }
        __syncthreads();

        // ---- S = Q @ K^T (128x128x64), warp layout 2(m) x 4(n) ----
        float acc_s[4][4][4] = {};
        #pragma unroll
        for (int k0 = 0; k0 < 64; k0 += 8) {
            unsigned af[4][4], bf[4][2];
            #pragma unroll
            for (int mi = 0; mi < 4; mi++) {
                int r = wm * 64 + mi * 16 + g;
                af[mi][0] = f2tf(Qs[(r    ) * FQS + k0 + t4    ]);
                af[mi][1] = f2tf(Qs[(r + 8) * FQS + k0 + t4    ]);
                af[mi][2] = f2tf(Qs[(r    ) * FQS + k0 + t4 + 4]);
                af[mi][3] = f2tf(Qs[(r + 8) * FQS + k0 + t4 + 4]);
            }
            #pragma unroll
            for (int ni = 0; ni < 4; ni++) {
                int n = wn * 32 + ni * 8 + g;
                bf[ni][0] = f2tf(Ks[n * FQS + k0 + t4    ]);
                bf[ni][1] = f2tf(Ks[n * FQS + k0 + t4 + 4]);
            }
            #pragma unroll
            for (int mi = 0; mi < 4; mi++)
                #pragma unroll
                for (int ni = 0; ni < 4; ni++)
                    MMA_TF32(acc_s[mi][ni], af[mi], bf[ni]);
        }

        // ---- write S to smem with scale + bias/mask ----
        #pragma unroll
        for (int mi = 0; mi < 4; mi++) {
            int rl = wm * 64 + mi * 16 + g;
            #pragma unroll
            for (int ni = 0; ni < 4; ni++) {
                int cc = wn * 32 + ni * 8 + t4 * 2;
                int j = j0 + cc;
                float s0 = acc_s[mi][ni][0] * scale;
                float s1 = acc_s[mi][ni][1] * scale;
                float s2 = acc_s[mi][ni][2] * scale;
                float s3 = acc_s[mi][ni][3] * scale;
                if (j < Nk) {
                    if (CAUSAL) {
                        s0 += bias[((size_t)(h * Nn + i0 + rl    )) * NK1 + j];
                        s2 += bias[((size_t)(h * Nn + i0 + rl + 8)) * NK1 + j];
                    }
                } else { s0 = -3.0e38f; s2 = -3.0e38f; }
                if (j + 1 < Nk) {
                    if (CAUSAL) {
                        s1 += bias[((size_t)(h * Nn + i0 + rl    )) * NK1 + j + 1];
                        s3 += bias[((size_t)(h * Nn + i0 + rl + 8)) * NK1 + j + 1];
                    }
                } else { s1 = -3.0e38f; s3 = -3.0e38f; }
                Ps[(rl    ) * FPS + cc    ] = s0;
                Ps[(rl    ) * FPS + cc + 1] = s1;
                Ps[(rl + 8) * FPS + cc    ] = s2;
                Ps[(rl + 8) * FPS + cc + 1] = s3;
            }
        }
        __syncthreads();

        // ---- online softmax: warp `wid` owns rows wid*16 .. wid*16+15 ----
        #pragma unroll
        for (int jr = 0; jr < 16; jr++) {
            int r = wid * 16 + jr;
            float* pr = Ps + (size_t)r * FPS;
            float v0 = pr[lane], v1 = pr[lane + 32], v2 = pr[lane + 64], v3 = pr[lane + 96];
            float tm = fmaxf(fmaxf(v0, v1), fmaxf(v2, v3));
            tm = warpMax(tm);
            float mn = fmaxf(m_st[jr], tm);
            float f = __expf(m_st[jr] - mn);
            v0 = __expf(v0 - mn); v1 = __expf(v1 - mn);
            v2 = __expf(v2 - mn); v3 = __expf(v3 - mn);
            pr[lane] = v0; pr[lane + 32] = v1; pr[lane + 64] = v2; pr[lane + 96] = v3;
            float ts = warpSum(v0 + v1 + v2 + v3);
            l_st[jr] = l_st[jr] * f + ts;
            m_st[jr] = mn;
            if (lane == 0) rowScale[r] = f;
        }
        __syncthreads();

        // ---- rescale O, then O += P @ V (128x64x128) ----
        #pragma unroll
        for (int mi = 0; mi < 4; mi++) {
            int rl = wm * 64 + mi * 16 + g;
            float f0 = rowScale[rl], f1 = rowScale[rl + 8];
            #pragma unroll
            for (int ni = 0; ni < 2; ni++) {
                acc_o[mi][ni][0] *= f0; acc_o[mi][ni][1] *= f0;
                acc_o[mi][ni][2] *= f1; acc_o[mi][ni][3] *= f1;
            }
        }
        #pragma unroll
        for (int k0 = 0; k0 < 128; k0 += 8) {
            unsigned af[4][4], bf[2][2];
            #pragma unroll
            for (int mi = 0; mi < 4; mi++) {
                int r = wm * 64 + mi * 16 + g;
                af[mi][0] = f2tf(Ps[(r    ) * FPS + k0 + t4    ]);
                af[mi][1] = f2tf(Ps[(r + 8) * FPS + k0 + t4    ]);
                af[mi][2] = f2tf(Ps[(r    ) * FPS + k0 + t4 + 4]);
                af[mi][3] = f2tf(Ps[(r + 8) * FPS + k0 + t4 + 4]);
            }
            #pragma unroll
            for (int ni = 0; ni < 2; ni++) {
                int n = wn * 16 + ni * 8 + g;
                bf[ni][0] = f2tf(Vs[(k0 + t4    ) * FQS + n]);
                bf[ni][1] = f2tf(Vs[(k0 + t4 + 4) * FQS + n]);
            }
            #pragma unroll
            for (int mi = 0; mi < 4; mi++)
                #pragma unroll
                for (int ni = 0; ni < 2; ni++)
                    MMA_TF32(acc_o[mi][ni], af[mi], bf[ni]);
        }
        __syncthreads();
    }

    // ---- publish row sums, normalize, write O ----
    #pragma unroll
    for (int jr = 0; jr < 16; jr++)
        if (lane == 0) rowSum[wid * 16 + jr] = l_st[jr];
    __syncthreads();

    #pragma unroll
    for (int mi = 0; mi < 4; mi++) {
        int rl = wm * 64 + mi * 16 + g;
        float inv0 = 1.f / rowSum[rl], inv1 = 1.f / rowSum[rl + 8];
        #pragma unroll
        for (int ni = 0; ni < 2; ni++) {
            int c = wn * 16 + ni * 8 + t4 * 2;
            float2 a0 = { acc_o[mi][ni][0] * inv0, acc_o[mi][ni][1] * inv0 };
            float2 a1 = { acc_o[mi][ni][2] * inv1, acc_o[mi][ni][3] * inv1 };
            *(float2*)&Op[(((size_t)(b * Nn + i0 + rl    )) * Hn + h) * DHn + c] = a0;
            *(float2*)&Op[(((size_t)(b * Nn + i0 + rl + 8)) * Hn + h) * DHn + c] = a1;
        }
    }
}

// ---------------- layernorm family ----------------
__global__ void ln_k(const float* __restrict__ x, const float* __restrict__ g,
                     float* __restrict__ out, int C)
{
    size_t row = blockIdx.x;
    const float* xr = x + row * C;
    float s = 0.f;
    for (int c = threadIdx.x; c < C; c += blockDim.x) s += xr[c];
    float mu = blockSum(s) / C;
    float v = 0.f;
    for (int c = threadIdx.x; c < C; c += blockDim.x) { float d = xr[c] - mu; v += d * d; }
    float rstd = rsqrtf(blockSum(v) / C + 1e-5f);
    float* orow = out + row * C;
    for (int c = threadIdx.x; c < C; c += blockDim.x) orow[c] = (xr[c] - mu) * rstd * g[c];
}

__global__ void lnadd_k(const float* __restrict__ p, const float* __restrict__ g,
                        float* __restrict__ x, int C)
{
    size_t row = blockIdx.x;
    const float* pr = p + row * C;
    float s = 0.f;
    for (int c = threadIdx.x; c < C; c += blockDim.x) s += pr[c];
    float mu = blockSum(s) / C;
    float v = 0.f;
    for (int c = threadIdx.x; c < C; c += blockDim.x) { float d = pr[c] - mu; v += d * d; }
    float rstd = rsqrtf(blockSum(v) / C + 1e-5f);
    float* xr = x + row * C;
    for (int c = threadIdx.x; c < C; c += blockDim.x) xr[c] += (pr[c] - mu) * rstd * g[c];
}

__global__ void lnfinal_k(const float* __restrict__ x, const float* __restrict__ g,
                          float* __restrict__ out)
{
    const int C = Dn;
    size_t row = blockIdx.x;
    const float* xr = x + row * C;
    float m = -3.4e38f;
    for (int c = threadIdx.x; c < C; c += blockDim.x) m = fmaxf(m, xr[c]);
    m = blockMax(m);
    float inv = 1.f / m;
    float s = 0.f;
    for (int c = threadIdx.x; c < C; c += blockDim.x) s += xr[c] * inv;
    float mu = blockSum(s) / C;
    float v = 0.f;
    for (int c = threadIdx.x; c < C; c += blockDim.x) { float d = xr[c] * inv - mu; v += d * d; }
    float rstd = rsqrtf(blockSum(v) / C + 1e-5f);
    float* orow = out + row * C;
    for (int c = threadIdx.x; c < C; c += blockDim.x) orow[c] = (xr[c] * inv - mu) * rstd * g[c];
}

// ---------------- rotary on q ----------------
__global__ void rotq_k(const float* __restrict__ q, float* __restrict__ o)
{
    size_t idx = (size_t)blockIdx.x * blockDim.x + threadIdx.x;
    if (idx >= (size_t)Bn * Nn * Hn * DHn) return;
    int c = (int)(idx & 63);
    float val = q[idx];
    if (c < 32) {
        int n = (int)((idx >> 9) & (Nn - 1));
        int p = c & 15;
        float invf = powf(10000.f, -(float)p / 16.f);
        float f = (float)n * invf;
        float partner = (c < 16) ? q[idx + 16] : q[idx - 16];
        val = val * cosf(f) + ((c < 16) ? -partner : partner) * sinf(f);
    }
    o[idx] = val;
}

// ---------------- assemble K/V ----------------
__global__ void asmkv_k(const float* __restrict__ kvt, const float* __restrict__ nkv,
                        float* __restrict__ kb, float* __restrict__ vb,
                        int Nsrc, int useRot)
{
    int NkL = Nsrc + 1;
    size_t total = (size_t)Bn * NkL * DHn;
    size_t idx = (size_t)blockIdx.x * blockDim.x + threadIdx.x;
    if (idx >= total) return;
    int c = (int)(idx & 63);
    size_t bj = idx >> 6;
    int j = (int)(bj % NkL);
    float kv, vv;
    if (j == 0) {
        kv = nkv[c];
        vv = nkv[DHn + c];
    } else {
        const float* rp = kvt + ((bj / NkL) * Nsrc + (j - 1)) * (size_t)(2 * DHn);
        kv = rp[c];
        vv = rp[DHn + c];
        if (useRot && c < 32) {
            int p = c & 15;
            float invf = powf(10000.f, -(float)p / 16.f);
            float f = (float)(j - 1) * invf;
            float partner = (c < 16) ? rp[c + 16] : rp[c - 16];
            kv = kv * cosf(f) + ((c < 16) ? -partner : partner) * sinf(f);
        }
    }
    kb[idx] = kv;
    vb[idx] = vv;
}

// ---------------- rel-pos bias + causal mask ----------------
__global__ void bias_k(const float* __restrict__ emb, float* __restrict__ bias)
{
    size_t total = (size_t)Hn * Nn * NK1;
    size_t idx = (size_t)blockIdx.x * blockDim.x + threadIdx.x;
    if (idx >= total) return;
    int j = (int)(idx % NK1);
    size_t r = idx / NK1;
    int i = (int)(r % Nn);
    int h = (int)(r / Nn);
    float v;
    if (j > i + 1) {
        v = -1e30f;
    } else {
        int n = i - j; if (n < 0) n = 0;
        int bucket;
        if (n < 16) bucket = n;
        else {
            float lf = logf((float)n * (1.f / 16.f)) * (16.f / logf(8.f));
            bucket = 16 + (int)lf;
            if (bucket > 31) bucket = 31;
        }
        v = emb[bucket * Hn + h];
    }
    bias[idx] = v;
}

// ---------------- swiglu ----------------
__global__ void swiglu_k(const float* __restrict__ ff1, float* __restrict__ out)
{
    size_t total = (size_t)Bn * Nn * FIn;
    size_t idx = (size_t)blockIdx.x * blockDim.x + threadIdx.x;
    if (idx >= total) return;
    size_t row = idx / FIn;
    int c = (int)(idx - row * FIn);
    float h = ff1[row * (2 * FIn) + c];
    float gt = ff1[row * (2 * FIn) + FIn + c];
    out[idx] = h * (gt / (1.f + expf(-gt)));
}

// ---------------- host orchestration ----------------
#define GSMEM_BYTES (GS * STAGEF * 4)
#define FSMEM_BYTES (FSM_TOT * 4)

static inline void gemm(const float* A, const float* B, float* C,
                        int M, int N, int K, int accum)
{
    dim3 gr(N / 128, M / 128);
    if (accum) gemm2_k<1><<<gr, 256, GSMEM_BYTES>>>(A, B, C, M, N, K);
    else       gemm2_k<0><<<gr, 256, GSMEM_BYTES>>>(A, B, C, M, N, K);
}

extern "C" void kernel_launch(void* const* d_in, const int* in_sizes, int n_in,
                              void* d_out, int out_size)
{
    (void)in_sizes; (void)n_in; (void)out_size;
    const float* in_x      = (const float*)d_in[0];
    const float* in_ctx    = (const float*)d_in[1];
    const float* in_relemb = (const float*)d_in[2];
    const float* in_sa_ng  = (const float*)d_in[3];
    const float* in_sa_wq  = (const float*)d_in[4];
    const float* in_sa_wkv = (const float*)d_in[5];
    const float* in_sa_nkv = (const float*)d_in[6];
    const float* in_sa_wo  = (const float*)d_in[7];
    const float* in_sa_og  = (const float*)d_in[8];
    const float* in_ca_ng  = (const float*)d_in[9];
    const float* in_ca_cg  = (const float*)d_in[10];
    const float* in_ca_wq  = (const float*)d_in[11];
    const float* in_ca_wkv = (const float*)d_in[12];
    const float* in_ca_nkv = (const float*)d_in[13];
    const float* in_ca_wo  = (const float*)d_in[14];
    const float* in_ca_og  = (const float*)d_in[15];
    const float* in_ff_ng  = (const float*)d_in[16];
    const float* in_ff_w1  = (const float*)d_in[17];
    const float* in_ff_w2  = (const float*)d_in[18];
    const float* in_norm_g = (const float*)d_in[19];
    float* out = (float*)d_out;

    // idempotent host-side attribute setup (no static guards allowed)
    cudaFuncSetAttribute(gemm2_k<0>, cudaFuncAttributeMaxDynamicSharedMemorySize, GSMEM_BYTES);
    cudaFuncSetAttribute(gemm2_k<1>, cudaFuncAttributeMaxDynamicSharedMemorySize, GSMEM_BYTES);
    cudaFuncSetAttribute(flash_k<0>, cudaFuncAttributeMaxDynamicSharedMemorySize, FSMEM_BYTES);
    cudaFuncSetAttribute(flash_k<1>, cudaFuncAttributeMaxDynamicSharedMemorySize, FSMEM_BYTES);

    float *px, *pxn, *pctxn, *pq, *pq2, *pkvt, *pk, *pv, *patt, *pproj, *pff1, *pffh, *pbias;
    cudaGetSymbolAddress((void**)&px,    g_x);
    cudaGetSymbolAddress((void**)&pxn,   g_xn);
    cudaGetSymbolAddress((void**)&pctxn, g_ctxn);
    cudaGetSymbolAddress((void**)&pq,    g_q);
    cudaGetSymbolAddress((void**)&pq2,   g_q2);
    cudaGetSymbolAddress((void**)&pkvt,  g_kvt);
    cudaGetSymbolAddress((void**)&pk,    g_k);
    cudaGetSymbolAddress((void**)&pv,    g_v);
    cudaGetSymbolAddress((void**)&patt,  g_att);
    cudaGetSymbolAddress((void**)&pproj, g_proj);
    cudaGetSymbolAddress((void**)&pff1,  g_ff1);
    cudaGetSymbolAddress((void**)&pffh,  g_ffh);
    cudaGetSymbolAddress((void**)&pbias, g_bias);

    const int rowsX = Bn * Nn;   // 4096
    const int rowsC = Bn * Mn;   // 2048

    cudaMemcpyAsync(px, in_x, sizeof(float) * (size_t)rowsX * Dn, cudaMemcpyDeviceToDevice);
    bias_k<<<CDIV((size_t)Hn * Nn * NK1, 256), 256>>>(in_relemb, pbias);

    for (int l = 0; l < Ln; l++) {
        const float* sa_ng  = in_sa_ng  + (size_t)l * Dn;
        const float* sa_wq  = in_sa_wq  + (size_t)l * Dn * Dn;
        const float* sa_wkv = in_sa_wkv + (size_t)l * Dn * 2 * DHn;
        const float* sa_nkv = in_sa_nkv + (size_t)l * 2 * DHn;
        const float* sa_wo  = in_sa_wo  + (size_t)l * Dn * Dn;
        const float* sa_og  = in_sa_og  + (size_t)l * Dn;
        const float* ca_ng  = in_ca_ng  + (size_t)l * Dn;
        const float* ca_cg  = in_ca_cg  + (size_t)l * Pn;
        const float* ca_wq  = in_ca_wq  + (size_t)l * Dn * Dn;
        const float* ca_wkv = in_ca_wkv + (size_t)l * Pn * 2 * DHn;
        const float* ca_nkv = in_ca_nkv + (size_t)l * 2 * DHn;
        const float* ca_wo  = in_ca_wo  + (size_t)l * Dn * Dn;
        const float* ca_og  = in_ca_og  + (size_t)l * Dn;
        const float* ff_ng  = in_ff_ng  + (size_t)l * Dn;
        const float* ff_w1  = in_ff_w1  + (size_t)l * Dn * 2 * FIn;
        const float* ff_w2  = in_ff_w2  + (size_t)l * FIn * Dn;

        // ===== self attention =====
        ln_k<<<rowsX, 256>>>(px, sa_ng, pxn, Dn);
        gemm(pxn, sa_wq,  pq,   rowsX, Hn * DHn, Dn, 0);
        gemm(pxn, sa_wkv, pkvt, rowsX, 2 * DHn,  Dn, 0);
        rotq_k<<<CDIV((size_t)Bn * Nn * Hn * DHn, 256), 256>>>(pq, pq2);
        asmkv_k<<<CDIV((size_t)Bn * NK1 * DHn, 256), 256>>>(pkvt, sa_nkv, pk, pv, Nn, 1);
        flash_k<1><<<dim3(Nn / 128, Bn * Hn), 256, FSMEM_BYTES>>>(pq2, pk, pv, pbias, patt, NK1);
        gemm(patt, sa_wo, pproj, rowsX, Dn, Dn, 0);
        lnadd_k<<<rowsX, 256>>>(pproj, sa_og, px, Dn);

        // ===== cross attention =====
        ln_k<<<rowsX, 256>>>(px, ca_ng, pxn, Dn);
        ln_k<<<rowsC, 256>>>(in_ctx, ca_cg, pctxn, Pn);
        gemm(pxn,   ca_wq,  pq,   rowsX, Hn * DHn, Dn, 0);
        gemm(pctxn, ca_wkv, pkvt, rowsC, 2 * DHn,  Pn, 0);
        asmkv_k<<<CDIV((size_t)Bn * NK2 * DHn, 256), 256>>>(pkvt, ca_nkv, pk, pv, Mn, 0);
        flash_k<0><<<dim3(Nn / 128, Bn * Hn), 256, FSMEM_BYTES>>>(pq, pk, pv, nullptr, patt, NK2);
        gemm(patt, ca_wo, pproj, rowsX, Dn, Dn, 0);
        lnadd_k<<<rowsX, 256>>>(pproj, ca_og, px, Dn);

        // ===== feed forward =====
        ln_k<<<rowsX, 256>>>(px, ff_ng, pxn, Dn);
        gemm(pxn, ff_w1, pff1, rowsX, 2 * FIn, Dn, 0);
        swiglu_k<<<CDIV((size_t)Bn * Nn * FIn, 256), 256>>>(pff1, pffh);
        gemm(pffh, ff_w2, px, rowsX, Dn, FIn, 1);
    }

    lnfinal_k<<<rowsX, 256>>>(px, in_norm_g, out);
}

// round 15
// speedup vs baseline: 3.6999x; 1.1028x over previous
#include <cuda_runtime.h>
#include <stdint.h>
#include <stddef.h>
#include <math.h>

// ---------------- problem constants ----------------
#define Bn 4
#define Nn 1024
#define Mn 512
#define Dn 512
#define Pn 256
#define Hn 8
#define DHn 64
#define Ln 6
#define FIn 2048
#define NK1 1025   // N + 1 (null kv)
#define NK2 513    // M + 1
#define QKVW 640   // fused SA qkv output width
#define CAW 768    // 6 layers * 128 CA kv width

#define CDIV(a,b) (((a)+(b)-1)/(b))

// ---------------- scratch (device globals; no allocation) ----------------
__device__ float g_x    [Bn*Nn*Dn];
__device__ float g_xn   [Bn*Nn*Dn];
__device__ float g_ctxn [Bn*Mn*Pn];
__device__ float g_q    [Bn*Nn*Hn*DHn];     // CA q projection
__device__ float g_q2   [Bn*Nn*Hn*DHn];     // SA rotated q
__device__ float g_qkv  [Bn*Nn*QKVW];       // fused SA q|kv projection
__device__ float g_cakv [(size_t)Bn*Mn*CAW];// all-layer CA kv projections
__device__ float g_k    [Bn*NK1*DHn];
__device__ float g_v    [Bn*NK1*DHn];
__device__ float g_att  [Bn*Nn*Hn*DHn];
__device__ float g_proj [Bn*Nn*Dn];
__device__ float g_ffh  [(size_t)Bn*Nn*FIn];
__device__ float g_bias [(size_t)Hn*Nn*NK1];
__device__ float g_wqkv [(size_t)Ln*Dn*QKVW];    // packed [wq|wkv] per layer
__device__ float g_w1p  [(size_t)Ln*Dn*2*FIn];   // interleaved h/gate w1
__device__ float g_wckv [(size_t)Pn*CAW];        // gain-folded, concatenated CA wkv

// ---------------- reductions ----------------
__device__ __forceinline__ float warpSum(float v) {
    #pragma unroll
    for (int o = 16; o > 0; o >>= 1) v += __shfl_xor_sync(0xffffffffu, v, o);
    return v;
}
__device__ __forceinline__ float warpMax(float v) {
    #pragma unroll
    for (int o = 16; o > 0; o >>= 1) v = fmaxf(v, __shfl_xor_sync(0xffffffffu, v, o));
    return v;
}
__device__ float blockSum(float v) {
    __shared__ float sh[32];
    int lane = threadIdx.x & 31, w = threadIdx.x >> 5;
    int nw = blockDim.x >> 5;
    v = warpSum(v);
    __syncthreads();
    if (lane == 0) sh[w] = v;
    __syncthreads();
    float r = (lane < nw) ? sh[lane] : 0.f;
    return warpSum(r);
}
__device__ float blockMax(float v) {
    __shared__ float sh[32];
    int lane = threadIdx.x & 31, w = threadIdx.x >> 5;
    int nw = blockDim.x >> 5;
    v = warpMax(v);
    __syncthreads();
    if (lane == 0) sh[w] = v;
    __syncthreads();
    float r = (lane < nw) ? sh[lane] : -3.4e38f;
    return warpMax(r);
}

__device__ __forceinline__ unsigned f2tf(float f) {
    unsigned u; asm("cvt.rna.tf32.f32 %0, %1;" : "=r"(u) : "f"(f)); return u;
}

#define MMA_TF32(ACC, AF, BF) \
    asm volatile( \
        "mma.sync.aligned.m16n8k8.row.col.f32.tf32.tf32.f32 " \
        "{%0,%1,%2,%3}, {%4,%5,%6,%7}, {%8,%9}, {%0,%1,%2,%3};" \
        : "+f"((ACC)[0]), "+f"((ACC)[1]), "+f"((ACC)[2]), "+f"((ACC)[3]) \
        : "r"((AF)[0]), "r"((AF)[1]), "r"((AF)[2]), "r"((AF)[3]), \
          "r"((BF)[0]), "r"((BF)[1]))

// =====================================================================
// Pipelined tf32 GEMM: C = A[M,K] @ B[K,N], row-major, lda=K, ldb=N.
// M%128==0, N%128==0, K%16==0. 3-stage cp.async, 128x128x16, 8 warps.
// EPI: 0 = store (ldc=N), 1 = accumulate (ldc=N),
//      2 = swiglu pairs: C[r][c/2] = acc_even * silu(acc_odd), ldc=N/2.
// =====================================================================
#define GS 3
#define SA 20
#define SB 132
#define STAGEF (128*SA + 16*SB)   // floats per stage

__device__ __forceinline__ void cp16(uint32_t s, const float* g) {
    asm volatile("cp.async.ca.shared.global [%0], [%1], 16;" :: "r"(s), "l"(g));
}

template<int EPI>
__global__ void __launch_bounds__(256, 2)
gemm2_k(const float* __restrict__ A, const float* __restrict__ B,
        float* __restrict__ C, int M, int N, int K)
{
    extern __shared__ float sm[];
    int row0 = blockIdx.y * 128, col0 = blockIdx.x * 128;
    int tid = threadIdx.x, lane = tid & 31, wid = tid >> 5;
    int wm = wid >> 2, wn = wid & 3, g = lane >> 2, t4 = lane & 3;
    int T = K >> 4;

    auto loadTile = [&](int t) {
        int k0 = t << 4;
        float* As = sm + (t % GS) * STAGEF;
        float* Bs = As + 128 * SA;
        uint32_t asu = (uint32_t)__cvta_generic_to_shared(As);
        uint32_t bsu = (uint32_t)__cvta_generic_to_shared(Bs);
        #pragma unroll
        for (int i = 0; i < 2; i++) {
            int ch = tid + i * 256;
            int r = ch >> 2, kc = (ch & 3) * 4;
            cp16(asu + (r * SA + kc) * 4, A + (size_t)(row0 + r) * K + k0 + kc);
        }
        #pragma unroll
        for (int i = 0; i < 2; i++) {
            int ch = tid + i * 256;
            int kr = ch >> 5, nc = (ch & 31) * 4;
            cp16(bsu + (kr * SB + nc) * 4, B + (size_t)(k0 + kr) * N + col0 + nc);
        }
    };

    float acc[4][4][4] = {};

    #pragma unroll
    for (int s = 0; s < GS - 1; s++) {
        if (s < T) loadTile(s);
        asm volatile("cp.async.commit_group;");
    }

    for (int t = 0; t < T; t++) {
        asm volatile("cp.async.wait_group %0;" :: "n"(GS - 2));
        __syncthreads();
        int nt = t + GS - 1;
        if (nt < T) loadTile(nt);
        asm volatile("cp.async.commit_group;");

        const float* As = sm + (t % GS) * STAGEF;
        const float* Bs = As + 128 * SA;
        #pragma unroll
        for (int ks = 0; ks < 2; ks++) {
            int k0 = ks * 8;
            unsigned af[4][4], bf[4][2];
            #pragma unroll
            for (int mi = 0; mi < 4; mi++) {
                int r = wm * 64 + mi * 16 + g;
                af[mi][0] = f2tf(As[(r    ) * SA + k0 + t4    ]);
                af[mi][1] = f2tf(As[(r + 8) * SA + k0 + t4    ]);
                af[mi][2] = f2tf(As[(r    ) * SA + k0 + t4 + 4]);
                af[mi][3] = f2tf(As[(r + 8) * SA + k0 + t4 + 4]);
            }
            #pragma unroll
            for (int ni = 0; ni < 4; ni++) {
                int n = wn * 32 + ni * 8 + g;
                bf[ni][0] = f2tf(Bs[(k0 + t4    ) * SB + n]);
                bf[ni][1] = f2tf(Bs[(k0 + t4 + 4) * SB + n]);
            }
            #pragma unroll
            for (int mi = 0; mi < 4; mi++)
                #pragma unroll
                for (int ni = 0; ni < 4; ni++)
                    MMA_TF32(acc[mi][ni], af[mi], bf[ni]);
        }
    }

    if (EPI == 2) {
        int ldc2 = N >> 1;
        #pragma unroll
        for (int mi = 0; mi < 4; mi++) {
            int r_ = row0 + wm * 64 + mi * 16 + g;
            #pragma unroll
            for (int ni = 0; ni < 4; ni++) {
                int c_ = col0 + wn * 32 + ni * 8 + t4 * 2;
                int j = c_ >> 1;
                float h0 = acc[mi][ni][0], g0 = acc[mi][ni][1];
                float h1 = acc[mi][ni][2], g1 = acc[mi][ni][3];
                C[(size_t)r_ * ldc2 + j]       = h0 * (g0 / (1.f + expf(-g0)));
                C[(size_t)(r_ + 8) * ldc2 + j] = h1 * (g1 / (1.f + expf(-g1)));
            }
        }
    } else {
        #pragma unroll
        for (int mi = 0; mi < 4; mi++) {
            int r_ = row0 + wm * 64 + mi * 16 + g;
            #pragma unroll
            for (int ni = 0; ni < 4; ni++) {
                int c_ = col0 + wn * 32 + ni * 8 + t4 * 2;
                size_t o0 = (size_t)r_ * N + c_;
                size_t o2 = (size_t)(r_ + 8) * N + c_;
                if (EPI == 1) {
                    C[o0]     += acc[mi][ni][0];
                    C[o0 + 1] += acc[mi][ni][1];
                    C[o2]     += acc[mi][ni][2];
                    C[o2 + 1] += acc[mi][ni][3];
                } else {
                    C[o0]     = acc[mi][ni][0];
                    C[o0 + 1] = acc[mi][ni][1];
                    C[o2]     = acc[mi][ni][2];
                    C[o2 + 1] = acc[mi][ni][3];
                }
            }
        }
    }
}

// =====================================================================
// Flash attention (unchanged from R10 pass)
// =====================================================================
#define FQS 68
#define FPS 132
#define FSM_K (128*FQS)
#define FSM_V (2*128*FQS)
#define FSM_P (3*128*FQS)
#define FSM_RS (FSM_P + 128*FPS)
#define FSM_RL (FSM_RS + 128)
#define FSM_TOT (FSM_RL + 128)

template<int CAUSAL>
__global__ void __launch_bounds__(256)
flash_k(const float* __restrict__ Qp, const float* __restrict__ Kp,
        const float* __restrict__ Vp, const float* __restrict__ bias,
        float* __restrict__ Op, int Nk)
{
    extern __shared__ float sm[];
    float* Qs = sm;
    float* Ks = sm + FSM_K;
    float* Vs = sm + FSM_V;
    float* Ps = sm + FSM_P;
    float* rowScale = sm + FSM_RS;
    float* rowSum   = sm + FSM_RL;

    const float scale = 0.125f;
    int qt = blockIdx.x, bh = blockIdx.y;
    int b = bh >> 3, h = bh & 7;
    int tid = threadIdx.x, lane = tid & 31, wid = tid >> 5;
    int wm = wid >> 2, wn = wid & 3, g = lane >> 2, t4 = lane & 3;
    int i0 = qt * 128;
    int nT = CAUSAL ? (qt + 2) : CDIV(Nk, 128);

    #pragma unroll
    for (int c = tid; c < 128 * 16; c += 256) {
        int r = c >> 4, dc = (c & 15) * 4;
        float4 v = *(const float4*)(Qp + (((size_t)(b * Nn + i0 + r)) * Hn + h) * DHn + dc);
        *(float4*)&Qs[r * FQS + dc] = v;
    }

    float m_st[16], l_st[16];
    #pragma unroll
    for (int jr = 0; jr < 16; jr++) { m_st[jr] = -3.0e38f; l_st[jr] = 0.f; }
    float acc_o[4][2][4] = {};

    for (int t = 0; t < nT; t++) {
        int j0 = t * 128;
        #pragma unroll
        for (int c = tid; c < 128 * 16; c += 256) {
            int r = c >> 4, dc = (c & 15) * 4;
            int j = j0 + r;
            float4 kv = {0.f,0.f,0.f,0.f}, vv = {0.f,0.f,0.f,0.f};
            if (j < Nk) {
                kv = *(const float4*)(Kp + ((size_t)b * Nk + j) * DHn + dc);
                vv = *(const float4*)(Vp + ((size_t)b * Nk + j) * DHn + dc);
            }
            *(float4*)&Ks[r * FQS + dc] = kv;
            *(float4*)&Vs[r * FQS + dc] = vv;
        }
        __syncthreads();

        float acc_s[4][4][4] = {};
        #pragma unroll
        for (int k0 = 0; k0 < 64; k0 += 8) {
            unsigned af[4][4], bf[4][2];
            #pragma unroll
            for (int mi = 0; mi < 4; mi++) {
                int r = wm * 64 + mi * 16 + g;
                af[mi][0] = f2tf(Qs[(r    ) * FQS + k0 + t4    ]);
                af[mi][1] = f2tf(Qs[(r + 8) * FQS + k0 + t4    ]);
                af[mi][2] = f2tf(Qs[(r    ) * FQS + k0 + t4 + 4]);
                af[mi][3] = f2tf(Qs[(r + 8) * FQS + k0 + t4 + 4]);
            }
            #pragma unroll
            for (int ni = 0; ni < 4; ni++) {
                int n = wn * 32 + ni * 8 + g;
                bf[ni][0] = f2tf(Ks[n * FQS + k0 + t4    ]);
                bf[ni][1] = f2tf(Ks[n * FQS + k0 + t4 + 4]);
            }
            #pragma unroll
            for (int mi = 0; mi < 4; mi++)
                #pragma unroll
                for (int ni = 0; ni < 4; ni++)
                    MMA_TF32(acc_s[mi][ni], af[mi], bf[ni]);
        }

        #pragma unroll
        for (int mi = 0; mi < 4; mi++) {
            int rl = wm * 64 + mi * 16 + g;
            #pragma unroll
            for (int ni = 0; ni < 4; ni++) {
                int cc = wn * 32 + ni * 8 + t4 * 2;
                int j = j0 + cc;
                float s0 = acc_s[mi][ni][0] * scale;
                float s1 = acc_s[mi][ni][1] * scale;
                float s2 = acc_s[mi][ni][2] * scale;
                float s3 = acc_s[mi][ni][3] * scale;
                if (j < Nk) {
                    if (CAUSAL) {
                        s0 += bias[((size_t)(h * Nn + i0 + rl    )) * NK1 + j];
                        s2 += bias[((size_t)(h * Nn + i0 + rl + 8)) * NK1 + j];
                    }
                } else { s0 = -3.0e38f; s2 = -3.0e38f; }
                if (j + 1 < Nk) {
                    if (CAUSAL) {
                        s1 += bias[((size_t)(h * Nn + i0 + rl    )) * NK1 + j + 1];
                        s3 += bias[((size_t)(h * Nn + i0 + rl + 8)) * NK1 + j + 1];
                    }
                } else { s1 = -3.0e38f; s3 = -3.0e38f; }
                Ps[(rl    ) * FPS + cc    ] = s0;
                Ps[(rl    ) * FPS + cc + 1] = s1;
                Ps[(rl + 8) * FPS + cc    ] = s2;
                Ps[(rl + 8) * FPS + cc + 1] = s3;
            }
        }
        __syncthreads();

        #pragma unroll
        for (int jr = 0; jr < 16; jr++) {
            int r = wid * 16 + jr;
            float* pr = Ps + (size_t)r * FPS;
            float v0 = pr[lane], v1 = pr[lane + 32], v2 = pr[lane + 64], v3 = pr[lane + 96];
            float tm = fmaxf(fmaxf(v0, v1), fmaxf(v2, v3));
            tm = warpMax(tm);
            float mn = fmaxf(m_st[jr], tm);
            float f = __expf(m_st[jr] - mn);
            v0 = __expf(v0 - mn); v1 = __expf(v1 - mn);
            v2 = __expf(v2 - mn); v3 = __expf(v3 - mn);
            pr[lane] = v0; pr[lane + 32] = v1; pr[lane + 64] = v2; pr[lane + 96] = v3;
            float ts = warpSum(v0 + v1 + v2 + v3);
            l_st[jr] = l_st[jr] * f + ts;
            m_st[jr] = mn;
            if (lane == 0) rowScale[r] = f;
        }
        __syncthreads();

        #pragma unroll
        for (int mi = 0; mi < 4; mi++) {
            int rl = wm * 64 + mi * 16 + g;
            float f0 = rowScale[rl], f1 = rowScale[rl + 8];
            #pragma unroll
            for (int ni = 0; ni < 2; ni++) {
                acc_o[mi][ni][0] *= f0; acc_o[mi][ni][1] *= f0;
                acc_o[mi][ni][2] *= f1; acc_o[mi][ni][3] *= f1;
            }
        }
        #pragma unroll
        for (int k0 = 0; k0 < 128; k0 += 8) {
            unsigned af[4][4], bf[2][2];
            #pragma unroll
            for (int mi = 0; mi < 4; mi++) {
                int r = wm * 64 + mi * 16 + g;
                af[mi][0] = f2tf(Ps[(r    ) * FPS + k0 + t4    ]);
                af[mi][1] = f2tf(Ps[(r + 8) * FPS + k0 + t4    ]);
                af[mi][2] = f2tf(Ps[(r    ) * FPS + k0 + t4 + 4]);
                af[mi][3] = f2tf(Ps[(r + 8) * FPS + k0 + t4 + 4]);
            }
            #pragma unroll
            for (int ni = 0; ni < 2; ni++) {
                int n = wn * 16 + ni * 8 + g;
                bf[ni][0] = f2tf(Vs[(k0 + t4    ) * FQS + n]);
                bf[ni][1] = f2tf(Vs[(k0 + t4 + 4) * FQS + n]);
            }
            #pragma unroll
            for (int mi = 0; mi < 4; mi++)
                #pragma unroll
                for (int ni = 0; ni < 2; ni++)
                    MMA_TF32(acc_o[mi][ni], af[mi], bf[ni]);
        }
        __syncthreads();
    }

    #pragma unroll
    for (int jr = 0; jr < 16; jr++)
        if (lane == 0) rowSum[wid * 16 + jr] = l_st[jr];
    __syncthreads();

    #pragma unroll
    for (int mi = 0; mi < 4; mi++) {
        int rl = wm * 64 + mi * 16 + g;
        float inv0 = 1.f / rowSum[rl], inv1 = 1.f / rowSum[rl + 8];
        #pragma unroll
        for (int ni = 0; ni < 2; ni++) {
            int c = wn * 16 + ni * 8 + t4 * 2;
            float2 a0 = { acc_o[mi][ni][0] * inv0, acc_o[mi][ni][1] * inv0 };
            float2 a1 = { acc_o[mi][ni][2] * inv1, acc_o[mi][ni][3] * inv1 };
            *(float2*)&Op[(((size_t)(b * Nn + i0 + rl    )) * Hn + h) * DHn + c] = a0;
            *(float2*)&Op[(((size_t)(b * Nn + i0 + rl + 8)) * Hn + h) * DHn + c] = a1;
        }
    }
}

// ---------------- layernorm family ----------------
__global__ void ln_k(const float* __restrict__ x, const float* __restrict__ g,
                     float* __restrict__ out, int C)
{
    size_t row = blockIdx.x;
    const float* xr = x + row * C;
    float s = 0.f;
    for (int c = threadIdx.x; c < C; c += blockDim.x) s += xr[c];
    float mu = blockSum(s) / C;
    float v = 0.f;
    for (int c = threadIdx.x; c < C; c += blockDim.x) { float d = xr[c] - mu; v += d * d; }
    float rstd = rsqrtf(blockSum(v) / C + 1e-5f);
    float* orow = out + row * C;
    for (int c = threadIdx.x; c < C; c += blockDim.x) orow[c] = (xr[c] - mu) * rstd * g[c];
}

// LN with unit gain (for context base)
__global__ void lnbase_k(const float* __restrict__ x, float* __restrict__ out, int C)
{
    size_t row = blockIdx.x;
    const float* xr = x + row * C;
    float s = 0.f;
    for (int c = threadIdx.x; c < C; c += blockDim.x) s += xr[c];
    float mu = blockSum(s) / C;
    float v = 0.f;
    for (int c = threadIdx.x; c < C; c += blockDim.x) { float d = xr[c] - mu; v += d * d; }
    float rstd = rsqrtf(blockSum(v) / C + 1e-5f);
    float* orow = out + row * C;
    for (int c = threadIdx.x; c < C; c += blockDim.x) orow[c] = (xr[c] - mu) * rstd;
}

__global__ void lnadd_k(const float* __restrict__ p, const float* __restrict__ g,
                        float* __restrict__ x, int C)
{
    size_t row = blockIdx.x;
    const float* pr = p + row * C;
    float s = 0.f;
    for (int c = threadIdx.x; c < C; c += blockDim.x) s += pr[c];
    float mu = blockSum(s) / C;
    float v = 0.f;
    for (int c = threadIdx.x; c < C; c += blockDim.x) { float d = pr[c] - mu; v += d * d; }
    float rstd = rsqrtf(blockSum(v) / C + 1e-5f);
    float* xr = x + row * C;
    for (int c = threadIdx.x; c < C; c += blockDim.x) xr[c] += (pr[c] - mu) * rstd * g[c];
}

__global__ void lnfinal_k(const float* __restrict__ x, const float* __restrict__ g,
                          float* __restrict__ out)
{
    const int C = Dn;
    size_t row = blockIdx.x;
    const float* xr = x + row * C;
    float m = -3.4e38f;
    for (int c = threadIdx.x; c < C; c += blockDim.x) m = fmaxf(m, xr[c]);
    m = blockMax(m);
    float inv = 1.f / m;
    float s = 0.f;
    for (int c = threadIdx.x; c < C; c += blockDim.x) s += xr[c] * inv;
    float mu = blockSum(s) / C;
    float v = 0.f;
    for (int c = threadIdx.x; c < C; c += blockDim.x) { float d = xr[c] * inv - mu; v += d * d; }
    float rstd = rsqrtf(blockSum(v) / C + 1e-5f);
    float* orow = out + row * C;
    for (int c = threadIdx.x; c < C; c += blockDim.x) orow[c] = (xr[c] * inv - mu) * rstd * g[c];
}

// ---------------- rotary on q (reads fused qkv buffer, stride QKVW) ----------------
__global__ void rotq_k(const float* __restrict__ qkv, float* __restrict__ o)
{
    size_t idx = (size_t)blockIdx.x * blockDim.x + threadIdx.x;
    if (idx >= (size_t)Bn * Nn * Hn * DHn) return;
    int c = (int)(idx & 63);
    size_t row = idx >> 9;              // b*Nn + n
    int col = (int)(idx & 511);         // h*64 + d
    const float* src = qkv + row * QKVW;
    float val = src[col];
    if (c < 32) {
        int n = (int)(row & (Nn - 1));
        int p = c & 15;
        float invf = powf(10000.f, -(float)p / 16.f);
        float f = (float)n * invf;
        float partner = (c < 16) ? src[col + 16] : src[col - 16];
        val = val * cosf(f) + ((c < 16) ? -partner : partner) * sinf(f);
    }
    o[idx] = val;
}

// ---------------- assemble K/V (generic source stride/offset) ----------------
__global__ void asmkv_k(const float* __restrict__ src, int lda, int colOff,
                        const float* __restrict__ nkv,
                        float* __restrict__ kb, float* __restrict__ vb,
                        int Nsrc, int useRot)
{
    int NkL = Nsrc + 1;
    size_t total = (size_t)Bn * NkL * DHn;
    size_t idx = (size_t)blockIdx.x * blockDim.x + threadIdx.x;
    if (idx >= total) return;
    int c = (int)(idx & 63);
    size_t bj = idx >> 6;
    int j = (int)(bj % NkL);
    float kv, vv;
    if (j == 0) {
        kv = nkv[c];
        vv = nkv[DHn + c];
    } else {
        const float* rp = src + ((bj / NkL) * Nsrc + (j - 1)) * (size_t)lda + colOff;
        kv = rp[c];
        vv = rp[DHn + c];
        if (useRot && c < 32) {
            int p = c & 15;
            float invf = powf(10000.f, -(float)p / 16.f);
            float f = (float)(j - 1) * invf;
            float partner = (c < 16) ? rp[c + 16] : rp[c - 16];
            kv = kv * cosf(f) + ((c < 16) ? -partner : partner) * sinf(f);
        }
    }
    kb[idx] = kv;
    vb[idx] = vv;
}

// ---------------- rel-pos bias + causal mask ----------------
__global__ void bias_k(const float* __restrict__ emb, float* __restrict__ bias)
{
    size_t total = (size_t)Hn * Nn * NK1;
    size_t idx = (size_t)blockIdx.x * blockDim.x + threadIdx.x;
    if (idx >= total) return;
    int j = (int)(idx % NK1);
    size_t r = idx / NK1;
    int i = (int)(r % Nn);
    int h = (int)(r / Nn);
    float v;
    if (j > i + 1) {
        v = -1e30f;
    } else {
        int n = i - j; if (n < 0) n = 0;
        int bucket;
        if (n < 16) bucket = n;
        else {
            float lf = logf((float)n * (1.f / 16.f)) * (16.f / logf(8.f));
            bucket = 16 + (int)lf;
            if (bucket > 31) bucket = 31;
        }
        v = emb[bucket * Hn + h];
    }
    bias[idx] = v;
}

// ---------------- weight packing kernels ----------------
// g_wqkv[l][k][c] = c<512 ? sa_wq[l][k][c] : sa_wkv[l][k][c-512]
__global__ void packqkv_k(const float* __restrict__ wq, const float* __restrict__ wkv,
                          float* __restrict__ out)
{
    size_t total = (size_t)Ln * Dn * QKVW;
    size_t idx = (size_t)blockIdx.x * blockDim.x + threadIdx.x;
    if (idx >= total) return;
    int c = (int)(idx % QKVW);
    size_t lk = idx / QKVW;           // l*Dn + k
    out[idx] = (c < 512) ? wq[lk * 512 + c] : wkv[lk * 128 + (c - 512)];
}

// g_w1p[l][k][2j]=w1[l][k][j], [2j+1]=w1[l][k][FIn+j]
__global__ void packw1_k(const float* __restrict__ w1, float* __restrict__ out)
{
    size_t total = (size_t)Ln * Dn * 2 * FIn;
    size_t idx = (size_t)blockIdx.x * blockDim.x + threadIdx.x;
    if (idx >= total) return;
    int c = (int)(idx % (2 * FIn));
    size_t lk = idx / (2 * FIn);
    int incol = (c & 1) ? (FIn + (c >> 1)) : (c >> 1);
    out[idx] = w1[lk * (2 * FIn) + incol];
}

// g_wckv[k][l*128+c] = ca_cg[l][k] * ca_wkv[l][k][c]
__global__ void packcakv_k(const float* __restrict__ cg, const float* __restrict__ wkv,
                           float* __restrict__ out)
{
    size_t total = (size_t)Pn * CAW;
    size_t idx = (size_t)blockIdx.x * blockDim.x + threadIdx.x;
    if (idx >= total) return;
    int c2 = (int)(idx % CAW);
    int k  = (int)(idx / CAW);
    int l  = c2 >> 7, c = c2 & 127;
    out[idx] = cg[l * Pn + k] * wkv[((size_t)l * Pn + k) * 128 + c];
}

// ---------------- host orchestration ----------------
#define GSMEM_BYTES (GS * STAGEF * 4)
#define FSMEM_BYTES (FSM_TOT * 4)

static inline void gemm(const float* A, const float* B, float* C,
                        int M, int N, int K, int epi)
{
    dim3 gr(N / 128, M / 128);
    if (epi == 2)      gemm2_k<2><<<gr, 256, GSMEM_BYTES>>>(A, B, C, M, N, K);
    else if (epi == 1) gemm2_k<1><<<gr, 256, GSMEM_BYTES>>>(A, B, C, M, N, K);
    else               gemm2_k<0><<<gr, 256, GSMEM_BYTES>>>(A, B, C, M, N, K);
}

extern "C" void kernel_launch(void* const* d_in, const int* in_sizes, int n_in,
                              void* d_out, int out_size)
{
    (void)in_sizes; (void)n_in; (void)out_size;
    const float* in_x      = (const float*)d_in[0];
    const float* in_ctx    = (const float*)d_in[1];
    const float* in_relemb = (const float*)d_in[2];
    const float* in_sa_ng  = (const float*)d_in[3];
    const float* in_sa_wq  = (const float*)d_in[4];
    const float* in_sa_wkv = (const float*)d_in[5];
    const float* in_sa_nkv = (const float*)d_in[6];
    const float* in_sa_wo  = (const float*)d_in[7];
    const float* in_sa_og  = (const float*)d_in[8];
    const float* in_ca_ng  = (const float*)d_in[9];
    const float* in_ca_cg  = (const float*)d_in[10];
    const float* in_ca_wq  = (const float*)d_in[11];
    const float* in_ca_wkv = (const float*)d_in[12];
    const float* in_ca_nkv = (const float*)d_in[13];
    const float* in_ca_wo  = (const float*)d_in[14];
    const float* in_ca_og  = (const float*)d_in[15];
    const float* in_ff_ng  = (const float*)d_in[16];
    const float* in_ff_w1  = (const float*)d_in[17];
    const float* in_ff_w2  = (const float*)d_in[18];
    const float* in_norm_g = (const float*)d_in[19];
    float* out = (float*)d_out;

    // idempotent host-side attribute setup (no static guards allowed)
    cudaFuncSetAttribute(gemm2_k<0>, cudaFuncAttributeMaxDynamicSharedMemorySize, GSMEM_BYTES);
    cudaFuncSetAttribute(gemm2_k<1>, cudaFuncAttributeMaxDynamicSharedMemorySize, GSMEM_BYTES);
    cudaFuncSetAttribute(gemm2_k<2>, cudaFuncAttributeMaxDynamicSharedMemorySize, GSMEM_BYTES);
    cudaFuncSetAttribute(flash_k<0>, cudaFuncAttributeMaxDynamicSharedMemorySize, FSMEM_BYTES);
    cudaFuncSetAttribute(flash_k<1>, cudaFuncAttributeMaxDynamicSharedMemorySize, FSMEM_BYTES);

    float *px, *pxn, *pctxn, *pq, *pq2, *pqkv, *pcakv, *pk, *pv, *patt, *pproj, *pffh, *pbias;
    float *pwqkv, *pw1p, *pwckv;
    cudaGetSymbolAddress((void**)&px,    g_x);
    cudaGetSymbolAddress((void**)&pxn,   g_xn);
    cudaGetSymbolAddress((void**)&pctxn, g_ctxn);
    cudaGetSymbolAddress((void**)&pq,    g_q);
    cudaGetSymbolAddress((void**)&pq2,   g_q2);
    cudaGetSymbolAddress((void**)&pqkv,  g_qkv);
    cudaGetSymbolAddress((void**)&pcakv, g_cakv);
    cudaGetSymbolAddress((void**)&pk,    g_k);
    cudaGetSymbolAddress((void**)&pv,    g_v);
    cudaGetSymbolAddress((void**)&patt,  g_att);
    cudaGetSymbolAddress((void**)&pproj, g_proj);
    cudaGetSymbolAddress((void**)&pffh,  g_ffh);
    cudaGetSymbolAddress((void**)&pbias, g_bias);
    cudaGetSymbolAddress((void**)&pwqkv, g_wqkv);
    cudaGetSymbolAddress((void**)&pw1p,  g_w1p);
    cudaGetSymbolAddress((void**)&pwckv, g_wckv);

    const int rowsX = Bn * Nn;   // 4096
    const int rowsC = Bn * Mn;   // 2048

    cudaMemcpyAsync(px, in_x, sizeof(float) * (size_t)rowsX * Dn, cudaMemcpyDeviceToDevice);
    bias_k<<<CDIV((size_t)Hn * Nn * NK1, 256), 256>>>(in_relemb, pbias);

    // pack weights (cheap, once per call)
    packqkv_k<<<CDIV((size_t)Ln * Dn * QKVW, 256), 256>>>(in_sa_wq, in_sa_wkv, pwqkv);
    packw1_k <<<CDIV((size_t)Ln * Dn * 2 * FIn, 256), 256>>>(in_ff_w1, pw1p);
    packcakv_k<<<CDIV((size_t)Pn * CAW, 256), 256>>>(in_ca_cg, in_ca_wkv, pwckv);

    // all-layer CA kv projections: base LN(ctx) once, one wide GEMM
    lnbase_k<<<rowsC, 256>>>(in_ctx, pctxn, Pn);
    gemm(pctxn, pwckv, pcakv, rowsC, CAW, Pn, 0);

    for (int l = 0; l < Ln; l++) {
        const float* sa_ng  = in_sa_ng  + (size_t)l * Dn;
        const float* sa_nkv = in_sa_nkv + (size_t)l * 2 * DHn;
        const float* sa_wo  = in_sa_wo  + (size_t)l * Dn * Dn;
        const float* sa_og  = in_sa_og  + (size_t)l * Dn;
        const float* ca_ng  = in_ca_ng  + (size_t)l * Dn;
        const float* ca_wq  = in_ca_wq  + (size_t)l * Dn * Dn;
        const float* ca_nkv = in_ca_nkv + (size_t)l * 2 * DHn;
        const float* ca_wo  = in_ca_wo  + (size_t)l * Dn * Dn;
        const float* ca_og  = in_ca_og  + (size_t)l * Dn;
        const float* ff_ng  = in_ff_ng  + (size_t)l * Dn;
        const float* ff_w2  = in_ff_w2  + (size_t)l * FIn * Dn;
        const float* wqkv_l = pwqkv + (size_t)l * Dn * QKVW;
        const float* w1p_l  = pw1p  + (size_t)l * Dn * 2 * FIn;

        // ===== self attention =====
        ln_k<<<rowsX, 256>>>(px, sa_ng, pxn, Dn);
        gemm(pxn, wqkv_l, pqkv, rowsX, QKVW, Dn, 0);
        rotq_k<<<CDIV((size_t)Bn * Nn * Hn * DHn, 256), 256>>>(pqkv, pq2);
        asmkv_k<<<CDIV((size_t)Bn * NK1 * DHn, 256), 256>>>(pqkv, QKVW, 512, sa_nkv, pk, pv, Nn, 1);
        flash_k<1><<<dim3(Nn / 128, Bn * Hn), 256, FSMEM_BYTES>>>(pq2, pk, pv, pbias, patt, NK1);
        gemm(patt, sa_wo, pproj, rowsX, Dn, Dn, 0);
        lnadd_k<<<rowsX, 256>>>(pproj, sa_og, px, Dn);

        // ===== cross attention =====
        ln_k<<<rowsX, 256>>>(px, ca_ng, pxn, Dn);
        gemm(pxn, ca_wq, pq, rowsX, Hn * DHn, Dn, 0);
        asmkv_k<<<CDIV((size_t)Bn * NK2 * DHn, 256), 256>>>(pcakv, CAW, l * 128, ca_nkv, pk, pv, Mn, 0);
        flash_k<0><<<dim3(Nn / 128, Bn * Hn), 256, FSMEM_BYTES>>>(pq, pk, pv, nullptr, patt, NK2);
        gemm(patt, ca_wo, pproj, rowsX, Dn, Dn, 0);
        lnadd_k<<<rowsX, 256>>>(pproj, ca_og, px, Dn);

        // ===== feed forward (swiglu fused into GEMM epilogue) =====
        ln_k<<<rowsX, 256>>>(px, ff_ng, pxn, Dn);
        gemm(pxn, w1p_l, pffh, rowsX, 2 * FIn, Dn, 2);
        gemm(pffh, ff_w2, px, rowsX, Dn, FIn, 1);
    }

    lnfinal_k<<<rowsX, 256>>>(px, in_norm_g, out);
}